// round 15
// baseline (speedup 1.0000x reference)
#include <cuda_runtime.h>
#include <cuda_fp16.h>
#include <cstdint>
#include <cstdio>

#define B_  16
#define N_  512
#define M_  8
#define D_  768
#define H_  12
#define DH  64
#define QKVW 2304
__device__ __constant__ float kSCALE = 0.125f; // 64^{-0.5}

// ---------------- scratch ----------------
__device__ __half g_qkv  [B_ * N_ * QKVW];           // [q | k | v] half
__device__ __half g_att  [B_ * N_ * D_];             // out_self + out_sim
__device__ __half g_xh   [B_ * N_ * D_];             // x half
__device__ __half g_t    [B_ * N_ * H_ * D_];        // t[bn][h][768]
__device__ __half g_s    [H_ * B_ * N_ * D_];        // s[h][bn][768]
__device__ float  g_ls   [B_ * H_ * N_ * M_];        // raw sim logits
__device__ float  g_w    [H_ * B_ * N_ * M_];        // normalized sim weights
__device__ float  g_asum [H_ * B_ * N_];
__device__ __half g_wqkvt[QKVW * D_];                // [Wq^T ; Wkv^T]
__device__ __half g_wkvh [D_ * 2 * D_];              // Wkv row-major half
__device__ __half g_wpt  [D_ * D_];
__device__ float  g_bqkv [QKVW];                     // [bq ; bkv]

// ---------------- helpers ----------------
__device__ __forceinline__ void cp16(void* smem_dst, const void* gmem_src) {
    unsigned s = (unsigned)__cvta_generic_to_shared(smem_dst);
    asm volatile("cp.async.cg.shared.global [%0], [%1], 16;\n"
                 :: "r"(s), "l"(gmem_src));
}
#define CP_COMMIT() asm volatile("cp.async.commit_group;\n" ::: "memory")
#define CP_WAIT0()  asm volatile("cp.async.wait_group 0;\n" ::: "memory")
#define CP_WAIT1()  asm volatile("cp.async.wait_group 1;\n" ::: "memory")
#define CP_WAIT2()  asm volatile("cp.async.wait_group 2;\n" ::: "memory")

__device__ __forceinline__ void mma_f16(float d[4],
                                        unsigned a0, unsigned a1, unsigned a2, unsigned a3,
                                        unsigned b0, unsigned b1)
{
    asm volatile(
        "mma.sync.aligned.m16n8k16.row.col.f32.f16.f16.f32 "
        "{%0,%1,%2,%3}, {%4,%5,%6,%7}, {%8,%9}, {%0,%1,%2,%3};\n"
        : "+f"(d[0]), "+f"(d[1]), "+f"(d[2]), "+f"(d[3])
        : "r"(a0), "r"(a1), "r"(a2), "r"(a3), "r"(b0), "r"(b1));
}
__device__ __forceinline__ void ldm_x4(unsigned r[4], const __half* p) {
    unsigned a = (unsigned)__cvta_generic_to_shared(p);
    asm volatile("ldmatrix.sync.aligned.m8n8.x4.shared.b16 {%0,%1,%2,%3}, [%4];"
                 : "=r"(r[0]), "=r"(r[1]), "=r"(r[2]), "=r"(r[3]) : "r"(a));
}
__device__ __forceinline__ void ldm_x4t(unsigned r[4], const __half* p) {
    unsigned a = (unsigned)__cvta_generic_to_shared(p);
    asm volatile("ldmatrix.sync.aligned.m8n8.x4.trans.shared.b16 {%0,%1,%2,%3}, [%4];"
                 : "=r"(r[0]), "=r"(r[1]), "=r"(r[2]), "=r"(r[3]) : "r"(a));
}
__device__ __forceinline__ unsigned packh2(float x, float y) {
    __half2 t = __floats2half2_rn(x, y);
    return *(unsigned*)&t;
}

// ---------------- merged prep kernel ----------------
__global__ __launch_bounds__(256) void prep_weights(
    const float* __restrict__ Wq, const float* __restrict__ Wkv,
    const float* __restrict__ Wp,
    const float* __restrict__ bq, const float* __restrict__ bkv,
    __half* __restrict__ wqkvt, __half* __restrict__ wkvh,
    __half* __restrict__ wpt, float* __restrict__ bqkv)
{
    __shared__ float t[32][33];
    const int bid = blockIdx.x;
    const int tid = threadIdx.x;

    if (bid < 2304) {
        const float* W; __half* Wt; int K, Nn, bx, by;
        if (bid < 576)       { W = Wq;  Wt = wqkvt;                K = D_; Nn = D_;     bx = bid % 24;          by = bid / 24; }
        else if (bid < 1728) { W = Wkv; Wt = wqkvt + (size_t)D_ * D_; K = D_; Nn = 2 * D_; bx = (bid - 576) % 48;  by = (bid - 576) / 48; }
        else                 { W = Wp;  Wt = wpt;                  K = D_; Nn = D_;     bx = (bid - 1728) % 24; by = (bid - 1728) / 24; }
        const int k0 = by * 32, n0 = bx * 32;
        const int x = tid & 31, y = tid >> 5;
        #pragma unroll
        for (int i = 0; i < 32; i += 8)
            t[y + i][x] = W[(size_t)(k0 + y + i) * Nn + n0 + x];
        __syncthreads();
        #pragma unroll
        for (int i = 0; i < 32; i += 8)
            Wt[(size_t)(n0 + y + i) * K + k0 + x] = __float2half_rn(t[x][y + i]);
    } else if (bid < 3456) {
        int i = (bid - 2304) * 256 + tid;
        if (i < D_ * 2 * D_ / 4) {
            float4 v = ((const float4*)Wkv)[i];
            ((__half2*)wkvh)[2 * i]     = __floats2half2_rn(v.x, v.y);
            ((__half2*)wkvh)[2 * i + 1] = __floats2half2_rn(v.z, v.w);
        }
    } else {
        int i = (bid - 3456) * 256 + tid;
        if (i < D_) bqkv[i] = bq[i];
        else if (i < QKVW) bqkv[i] = bkv[i - D_];
    }
}

__global__ void f2h_kernel(const float* __restrict__ in,
                           __half* __restrict__ out, int n4) {
    int i = blockIdx.x * blockDim.x + threadIdx.x;
    if (i < n4) {
        float4 v = ((const float4*)in)[i];
        ((__half2*)out)[2 * i]     = __floats2half2_rn(v.x, v.y);
        ((__half2*)out)[2 * i + 1] = __floats2half2_rn(v.z, v.w);
    }
}

// ---------------- generalized fp16 GEMM + bias (256x128 tile, ldmatrix) ---------
#define SAH  40
#define ABYT (256 * SAH * 2)
#define BBYT (128 * SAH * 2)
#define STG  (ABYT + BBYT)
#define GEMM_SMEM (3 * STG)

template <typename OutT>
__global__ __launch_bounds__(256, 1) void hgemm_bias(
    const __half* __restrict__ A, int lda, long zA,
    const __half* __restrict__ Bt, int ldb, long zB,
    const float* __restrict__ bias,
    OutT* __restrict__ C, int ldc, long zC,
    int Kdim)
{
    extern __shared__ __half smem[];
    A  += (size_t)blockIdx.z * zA;
    Bt += (size_t)blockIdx.z * zB;
    C  += (size_t)blockIdx.z * zC;

    const int tid  = threadIdx.x;
    const int warp = tid >> 5;
    const int lane = tid & 31;
    const int gid  = lane >> 2;
    const int tig  = lane & 3;
    const int wm   = (warp >> 1) * 64;
    const int wn   = (warp & 1)  * 64;
    const int bm   = blockIdx.y * 256;
    const int bn   = blockIdx.x * 128;

    const int crow = tid >> 2;
    const int cg   = (tid & 3) << 3;
    const __half* Agp = A  + (size_t)(bm + crow) * lda + cg;
    const __half* Bgp = Bt + (size_t)(bn + crow) * ldb + cg;
    const size_t a64 = (size_t)64 * lda;
    const size_t b64 = (size_t)64 * ldb;

    const int ktiles = Kdim >> 5;

    auto load_stage = [&](int s, int t) {
        __half* as = smem + s * (STG / 2);
        __half* bs = as + ABYT / 2;
        const int k0 = t << 5;
        #pragma unroll
        for (int i = 0; i < 4; i++)
            cp16(&as[(crow + i * 64) * SAH + cg], Agp + i * a64 + k0);
        #pragma unroll
        for (int i = 0; i < 2; i++)
            cp16(&bs[(crow + i * 64) * SAH + cg], Bgp + i * b64 + k0);
    };

    float acc[4][8][4];
    #pragma unroll
    for (int mt = 0; mt < 4; mt++)
        #pragma unroll
        for (int nt = 0; nt < 8; nt++)
            #pragma unroll
            for (int c = 0; c < 4; c++) acc[mt][nt][c] = 0.f;

    load_stage(0, 0); CP_COMMIT();
    if (ktiles > 1) load_stage(1, 1);
    CP_COMMIT();

    const int a_off = (wm + (lane & 15)) * SAH + ((lane >> 4) << 3);
    const int b_off = (wn + ((lane >> 4) << 3) + (lane & 7)) * SAH
                    + (((lane >> 3) & 1) << 3);

    for (int t = 0; t < ktiles; t++) {
        if (t + 2 < ktiles) load_stage((t + 2) % 3, t + 2);
        CP_COMMIT();
        CP_WAIT2();
        __syncthreads();

        const __half* as = smem + (t % 3) * (STG / 2);
        const __half* bs = as + ABYT / 2;
        #pragma unroll
        for (int ks = 0; ks < 2; ks++) {
            const int kh = ks << 4;
            unsigned afr[4][4], bfr[4][4];
            #pragma unroll
            for (int mt = 0; mt < 4; mt++)
                ldm_x4(afr[mt], as + a_off + mt * 16 * SAH + kh);
            #pragma unroll
            for (int np = 0; np < 4; np++)
                ldm_x4(bfr[np], bs + b_off + np * 16 * SAH + kh);
            #pragma unroll
            for (int mt = 0; mt < 4; mt++)
                #pragma unroll
                for (int nt = 0; nt < 8; nt++) {
                    const unsigned* bp = bfr[nt >> 1];
                    const int e = (nt & 1) << 1;
                    mma_f16(acc[mt][nt],
                            afr[mt][0], afr[mt][1], afr[mt][2], afr[mt][3],
                            bp[e], bp[e + 1]);
                }
        }
        __syncthreads();
    }

    #pragma unroll
    for (int mt = 0; mt < 4; mt++) {
        const int row0 = bm + wm + mt * 16 + gid;
        #pragma unroll
        for (int nt = 0; nt < 8; nt++) {
            const int col = bn + wn + nt * 8 + 2 * tig;
            const float b0 = bias[col], b1 = bias[col + 1];
            if constexpr (sizeof(OutT) == 4) {
                float2 o0, o1;
                o0.x = acc[mt][nt][0] + b0; o0.y = acc[mt][nt][1] + b1;
                o1.x = acc[mt][nt][2] + b0; o1.y = acc[mt][nt][3] + b1;
                *(float2*)&C[(size_t)row0 * ldc + col]       = o0;
                *(float2*)&C[(size_t)(row0 + 8) * ldc + col] = o1;
            } else {
                *(__half2*)&C[(size_t)row0 * ldc + col] =
                    __floats2half2_rn(acc[mt][nt][0] + b0, acc[mt][nt][1] + b1);
                *(__half2*)&C[(size_t)(row0 + 8) * ldc + col] =
                    __floats2half2_rn(acc[mt][nt][2] + b0, acc[mt][nt][3] + b1);
            }
        }
    }
}

// ---------------- t-GEMM v3b: 128x64 tile, loops all 12 heads, double-buffered --
// Correct copy mapping: 8-half granules (16B), A 1024 granules, B 512 granules.
#define TST 72
#define TSTG ((128 + 64) * TST)             // halves per stage
#define TGEMM_SMEM (2 * TSTG * 2)           // 55296 B (dynamic)

__global__ __launch_bounds__(256) void hgemm_t(
    const __half* __restrict__ qkv,
    const __half* __restrict__ wkvh,
    __half* __restrict__ tt)
{
    extern __shared__ __half smt[];

    const int tid  = threadIdx.x;
    const int warp = tid >> 5;
    const int lane = tid & 31;
    const int gid  = lane >> 2;
    const int tig  = lane & 3;
    const int wm   = (warp >> 1) * 32;   // 0,32,64,96
    const int wn   = (warp & 1)  * 32;   // 0,32
    const int bm   = blockIdx.y * 128;
    const int bn   = blockIdx.x * 64;

    auto load_stage = [&](int s, int z) {
        __half* sA = smt + s * TSTG;
        __half* sB = sA + 128 * TST;
        // A: 128 rows x 8 granules (8 halves each) = 1024 -> 4 per thread
        #pragma unroll
        for (int i = 0; i < 4; i++) {
            const int idx = tid + i * 256;
            const int row = idx >> 3, g = (idx & 7) << 3;
            cp16(&sA[row * TST + g],
                 qkv + (size_t)(bm + row) * QKVW + z * DH + g);
        }
        // B: 64 rows x 8 granules = 512 -> 2 per thread
        #pragma unroll
        for (int i = 0; i < 2; i++) {
            const int idx = tid + i * 256;
            const int row = idx >> 3, g = (idx & 7) << 3;
            cp16(&sB[row * TST + g],
                 wkvh + (size_t)(bn + row) * (2 * D_) + z * DH + g);
        }
    };

    load_stage(0, 0); CP_COMMIT();

    const int a_off = (wm + (lane & 15)) * TST + ((lane >> 4) << 3);
    const int b_off = (wn + ((lane >> 4) << 3) + (lane & 7)) * TST
                    + (((lane >> 3) & 1) << 3);

    for (int z = 0; z < H_; z++) {
        if (z + 1 < H_) load_stage((z + 1) & 1, z + 1);
        CP_COMMIT();
        if (z + 1 < H_) { CP_WAIT1(); } else { CP_WAIT0(); }
        __syncthreads();

        const __half* sA = smt + (z & 1) * TSTG;
        const __half* sB = sA + 128 * TST;

        float acc[2][4][4];
        #pragma unroll
        for (int mt = 0; mt < 2; mt++)
            #pragma unroll
            for (int nt = 0; nt < 4; nt++)
                #pragma unroll
                for (int c = 0; c < 4; c++) acc[mt][nt][c] = 0.f;

        #pragma unroll
        for (int ks = 0; ks < 4; ks++) {
            const int kh = ks << 4;
            unsigned afr[2][4], bfr[2][4];
            #pragma unroll
            for (int mt = 0; mt < 2; mt++)
                ldm_x4(afr[mt], sA + a_off + mt * 16 * TST + kh);
            #pragma unroll
            for (int ng = 0; ng < 2; ng++)
                ldm_x4(bfr[ng], sB + b_off + ng * 16 * TST + kh);
            #pragma unroll
            for (int mt = 0; mt < 2; mt++)
                #pragma unroll
                for (int nt = 0; nt < 4; nt++) {
                    const unsigned* bp = bfr[nt >> 1];
                    const int e = (nt & 1) << 1;
                    mma_f16(acc[mt][nt],
                            afr[mt][0], afr[mt][1], afr[mt][2], afr[mt][3],
                            bp[e], bp[e + 1]);
                }
        }

        __half* C = tt + (size_t)z * D_;
        #pragma unroll
        for (int mt = 0; mt < 2; mt++) {
            const int row0 = bm + wm + mt * 16 + gid;
            #pragma unroll
            for (int nt = 0; nt < 4; nt++) {
                const int col = bn + wn + nt * 8 + 2 * tig;
                *(__half2*)&C[(size_t)row0 * (H_ * D_) + col] =
                    __floats2half2_rn(acc[mt][nt][0], acc[mt][nt][1]);
                *(__half2*)&C[(size_t)(row0 + 8) * (H_ * D_) + col] =
                    __floats2half2_rn(acc[mt][nt][2], acc[mt][nt][3]);
            }
        }
        __syncthreads();   // protect buffer (z+1)&1 before next load
    }
}

// ---------------- svw GEMM ----------------
#define SVW_ABYT (256 * SAH * 2)
#define SVW_BBYT (64 * SAH * 2)
#define SVW_STG  (SVW_ABYT + SVW_BBYT)
#define SVW_SMEM (3 * SVW_STG)

__global__ __launch_bounds__(256, 1) void hgemm_svw(
    const __half* __restrict__ S,
    const __half* __restrict__ Wkvt,
    const float* __restrict__ bkv,
    const float* __restrict__ asum,
    __half* __restrict__ att)
{
    extern __shared__ __half smem[];
    const int h = blockIdx.z;
    const __half* A  = S + (size_t)h * (B_ * N_) * D_;
    const __half* Bt = Wkvt + (size_t)(D_ + h * DH) * D_;
    const float* bv  = bkv + D_ + h * DH;
    const float* ash = asum + (size_t)h * (B_ * N_);

    const int tid  = threadIdx.x;
    const int warp = tid >> 5;
    const int lane = tid & 31;
    const int gid  = lane >> 2;
    const int tig  = lane & 3;
    const int wm   = warp * 32;
    const int bm   = blockIdx.y * 256;

    const int crow = tid >> 2;
    const int cg   = (tid & 3) << 3;
    const __half* Agp = A  + (size_t)(bm + crow) * D_ + cg;
    const __half* Bgp = Bt + (size_t)crow * D_ + cg;
    const size_t a64 = (size_t)64 * D_;

    const int ktiles = D_ >> 5;

    auto load_stage = [&](int s, int t) {
        __half* as = smem + s * (SVW_STG / 2);
        __half* bs = as + SVW_ABYT / 2;
        const int k0 = t << 5;
        #pragma unroll
        for (int i = 0; i < 4; i++)
            cp16(&as[(crow + i * 64) * SAH + cg], Agp + i * a64 + k0);
        cp16(&bs[crow * SAH + cg], Bgp + k0);
    };

    float acc[2][8][4];
    #pragma unroll
    for (int mt = 0; mt < 2; mt++)
        #pragma unroll
        for (int nt = 0; nt < 8; nt++)
            #pragma unroll
            for (int c = 0; c < 4; c++) acc[mt][nt][c] = 0.f;

    load_stage(0, 0); CP_COMMIT();
    load_stage(1, 1); CP_COMMIT();

    const int a_off = (wm + (lane & 15)) * SAH + ((lane >> 4) << 3);
    const int b_off = (((lane >> 4) << 3) + (lane & 7)) * SAH
                    + (((lane >> 3) & 1) << 3);

    for (int t = 0; t < ktiles; t++) {
        if (t + 2 < ktiles) load_stage((t + 2) % 3, t + 2);
        CP_COMMIT();
        CP_WAIT2();
        __syncthreads();

        const __half* as = smem + (t % 3) * (SVW_STG / 2);
        const __half* bs = as + SVW_ABYT / 2;
        #pragma unroll
        for (int ks = 0; ks < 2; ks++) {
            const int kh = ks << 4;
            unsigned afr[2][4], bfr[4][4];
            #pragma unroll
            for (int mt = 0; mt < 2; mt++)
                ldm_x4(afr[mt], as + a_off + mt * 16 * SAH + kh);
            #pragma unroll
            for (int np = 0; np < 4; np++)
                ldm_x4(bfr[np], bs + b_off + np * 16 * SAH + kh);
            #pragma unroll
            for (int mt = 0; mt < 2; mt++)
                #pragma unroll
                for (int nt = 0; nt < 8; nt++) {
                    const unsigned* bp = bfr[nt >> 1];
                    const int e = (nt & 1) << 1;
                    mma_f16(acc[mt][nt],
                            afr[mt][0], afr[mt][1], afr[mt][2], afr[mt][3],
                            bp[e], bp[e + 1]);
                }
        }
        __syncthreads();
    }

    #pragma unroll
    for (int mt = 0; mt < 2; mt++) {
        const int row0 = bm + wm + mt * 16 + gid;
        const float as0 = ash[row0], as1 = ash[row0 + 8];
        #pragma unroll
        for (int nt = 0; nt < 8; nt++) {
            const int col = nt * 8 + 2 * tig;
            const float b0 = bv[col], b1 = bv[col + 1];
            __half2* c0 = (__half2*)&att[(size_t)row0 * D_ + h * DH + col];
            __half2* c1 = (__half2*)&att[(size_t)(row0 + 8) * D_ + h * DH + col];
            float2 p0 = __half22float2(*c0);
            float2 p1 = __half22float2(*c1);
            *c0 = __floats2half2_rn(acc[mt][nt][0] + as0 * b0 + p0.x,
                                    acc[mt][nt][1] + as0 * b1 + p0.y);
            *c1 = __floats2half2_rn(acc[mt][nt][2] + as1 * b0 + p1.x,
                                    acc[mt][nt][3] + as1 * b1 + p1.y);
        }
    }
}

// ---------------- sim logits (fp32 sim input) ----------------
__global__ __launch_bounds__(256) void logits_sim_kernel(
    const float* __restrict__ sim,
    const __half* __restrict__ t,
    float* __restrict__ ls)
{
    __shared__ float  ssim[M_ * D_];
    __shared__ __half st[H_ * D_];
    const int bn = blockIdx.x;
    const int tid = threadIdx.x;
    const float4* sg = (const float4*)(sim + (size_t)bn * M_ * D_);
    float4* sd = (float4*)ssim;
    for (int i = tid; i < M_ * D_ / 4; i += 256) sd[i] = sg[i];
    const float4* tg = (const float4*)(t + (size_t)bn * H_ * D_);
    float4* td = (float4*)st;
    for (int i = tid; i < H_ * D_ / 8; i += 256) td[i] = tg[i];
    __syncthreads();

    const int warp = tid >> 5, lane = tid & 31;
    const int b = bn >> 9, n = bn & 511;
    const float2* s2 = (const float2*)ssim;
    const __half2* t2 = (const __half2*)st;
    for (int d = warp; d < H_ * M_; d += 8) {
        const int h = d >> 3, m = d & 7;
        float a = 0.f;
        #pragma unroll
        for (int j = 0; j < 12; j++) {
            float2 x = s2[m * 384 + lane + 32 * j];
            float2 y = __half22float2(t2[h * 384 + lane + 32 * j]);
            a += x.x * y.x + x.y * y.y;
        }
        #pragma unroll
        for (int o = 16; o; o >>= 1) a += __shfl_xor_sync(0xffffffffu, a, o);
        if (lane == 0)
            ls[(((size_t)b * H_ + h) * N_ + n) * M_ + m] = a;
    }
}

// ---------------- s-pass (fp32 sim input) ----------------
__global__ __launch_bounds__(256) void spass_kernel(
    const float* __restrict__ sim,
    const float* __restrict__ w,
    __half* __restrict__ s)
{
    __shared__ float ssim[M_ * D_];
    __shared__ float sw[H_ * M_];
    const int bn = blockIdx.x;
    const int tid = threadIdx.x;
    const float4* sg = (const float4*)(sim + (size_t)bn * M_ * D_);
    float4* sd = (float4*)ssim;
    for (int i = tid; i < M_ * D_ / 4; i += 256) sd[i] = sg[i];
    if (tid < H_ * M_) {
        int h = tid >> 3, m = tid & 7;
        sw[tid] = w[((size_t)h * (B_ * N_) + bn) * M_ + m];
    }
    __syncthreads();

    const float2* s2 = (const float2*)ssim;
    for (int idx = tid; idx < H_ * 384; idx += 256) {
        const int h = idx / 384, c2 = idx % 384;
        float ax = 0.f, ay = 0.f;
        #pragma unroll
        for (int m = 0; m < M_; m++) {
            float2 v = s2[m * 384 + c2];
            float wm_ = sw[h * M_ + m];
            ax += wm_ * v.x; ay += wm_ * v.y;
        }
        ((__half2*)s)[((size_t)h * (B_ * N_) + bn) * 384 + c2] =
            __floats2half2_rn(ax, ay);
    }
}

// ---------------- tensor-core flash attention (128 queries, 8 warps) ----------
#define SQV 72
#define QSZ (128 * SQV)
#define TSZ (64 * SQV)
#define ATTN_SMEM_MMA ((QSZ + 6 * TSZ) * 2)   // 73728 B

__global__ __launch_bounds__(256, 2) void attn_mma_kernel(
    const __half* __restrict__ qkv,
    const float*  __restrict__ bkv,
    const float*  __restrict__ ls,
    __half* __restrict__ outa,
    float* __restrict__ wg,
    float* __restrict__ asum)
{
    extern __shared__ __half smh[];
    __half* sQ = smh;
    __half* sK = sQ + QSZ;
    __half* sV = sK + 3 * TSZ;

    const int tid = threadIdx.x;
    const int warp = tid >> 5, lane = tid & 31;
    const int gid = lane >> 2, tig = lane & 3;
    const int n0 = blockIdx.x * 128, h = blockIdx.y, b = blockIdx.z;
    const int wq = warp * 16;
    const float scale = kSCALE;
    const int bn0 = b * N_ + n0;

    {
        const int row = tid >> 1, g0 = (tid & 1) << 5;
        const __half* src = qkv + (size_t)(bn0 + row) * QKVW + h * DH + g0;
        #pragma unroll
        for (int i = 0; i < 4; i++)
            cp16(&sQ[row * SQV + g0 + i * 8], src + i * 8);
    }
    auto load_tile = [&](int st, int kt) {
        const int row = tid >> 2, g = (tid & 3) << 4;
        size_t go = (size_t)(b * N_ + kt * 64 + row) * QKVW + D_ + h * DH + g;
        cp16(&sK[st * TSZ + row * SQV + g],     qkv + go);
        cp16(&sK[st * TSZ + row * SQV + g + 8], qkv + go + 8);
        cp16(&sV[st * TSZ + row * SQV + g],     qkv + go + D_);
        cp16(&sV[st * TSZ + row * SQV + g + 8], qkv + go + D_ + 8);
    };
    load_tile(0, 0); CP_COMMIT();
    load_tile(1, 1); CP_COMMIT();

    float m_[2] = {-1e30f, -1e30f}, l_[2] = {0.f, 0.f};
    float o[8][4];
    #pragma unroll
    for (int nt = 0; nt < 8; nt++)
        #pragma unroll
        for (int c = 0; c < 4; c++) o[nt][c] = 0.f;

    unsigned qa[4][4];
    const int a_off = (wq + (lane & 15)) * SQV + ((lane >> 4) << 3);
    const int kb_off = (((lane >> 4) << 3) + (lane & 7)) * SQV
                     + (((lane >> 3) & 1) << 3);
    const int vb_off = (((lane >> 3) & 1) * 8 + (lane & 7)) * SQV
                     + ((lane >> 4) << 3);
    bool qloaded = false;

    for (int kt = 0; kt < 8; kt++) {
        if (kt + 2 < 8) load_tile((kt + 2) % 3, kt + 2);
        CP_COMMIT();
        CP_WAIT2();
        __syncthreads();

        if (!qloaded) {
            #pragma unroll
            for (int ks = 0; ks < 4; ks++)
                ldm_x4(qa[ks], sQ + a_off + ks * 16);
            qloaded = true;
        }

        const __half* kb = sK + (kt % 3) * TSZ;
        const __half* vb = sV + (kt % 3) * TSZ;

        float sc[8][4];
        #pragma unroll
        for (int nt = 0; nt < 8; nt++)
            #pragma unroll
            for (int c = 0; c < 4; c++) sc[nt][c] = 0.f;
        #pragma unroll
        for (int ks = 0; ks < 4; ks++) {
            unsigned kf[4][4];
            #pragma unroll
            for (int ng = 0; ng < 4; ng++)
                ldm_x4(kf[ng], kb + kb_off + ng * 16 * SQV + ks * 16);
            #pragma unroll
            for (int nt = 0; nt < 8; nt++) {
                const unsigned* bp = kf[nt >> 1];
                const int e = (nt & 1) << 1;
                mma_f16(sc[nt], qa[ks][0], qa[ks][1], qa[ks][2], qa[ks][3],
                        bp[e], bp[e + 1]);
            }
        }
        #pragma unroll
        for (int nt = 0; nt < 8; nt++)
            #pragma unroll
            for (int c = 0; c < 4; c++) sc[nt][c] *= scale;

        #pragma unroll
        for (int s = 0; s < 2; s++) {
            const int e = s << 1;
            float tmax = -1e30f;
            #pragma unroll
            for (int nt = 0; nt < 8; nt++)
                tmax = fmaxf(tmax, fmaxf(sc[nt][e], sc[nt][e + 1]));
            tmax = fmaxf(tmax, __shfl_xor_sync(0xffffffffu, tmax, 1));
            tmax = fmaxf(tmax, __shfl_xor_sync(0xffffffffu, tmax, 2));
            float nm = fmaxf(m_[s], tmax);
            float corr = __expf(m_[s] - nm);
            float sum = 0.f;
            #pragma unroll
            for (int nt = 0; nt < 8; nt++) {
                sc[nt][e]     = __expf(sc[nt][e] - nm);
                sc[nt][e + 1] = __expf(sc[nt][e + 1] - nm);
                sum += sc[nt][e] + sc[nt][e + 1];
            }
            sum += __shfl_xor_sync(0xffffffffu, sum, 1);
            sum += __shfl_xor_sync(0xffffffffu, sum, 2);
            l_[s] = l_[s] * corr + sum;
            m_[s] = nm;
            #pragma unroll
            for (int nt = 0; nt < 8; nt++) {
                o[nt][e]     *= corr;
                o[nt][e + 1] *= corr;
            }
        }

        unsigned pa[4][4];
        #pragma unroll
        for (int kc = 0; kc < 4; kc++) {
            pa[kc][0] = packh2(sc[2 * kc][0],     sc[2 * kc][1]);
            pa[kc][1] = packh2(sc[2 * kc][2],     sc[2 * kc][3]);
            pa[kc][2] = packh2(sc[2 * kc + 1][0], sc[2 * kc + 1][1]);
            pa[kc][3] = packh2(sc[2 * kc + 1][2], sc[2 * kc + 1][3]);
        }

        #pragma unroll
        for (int kc = 0; kc < 4; kc++) {
            unsigned vf[4][4];
            #pragma unroll
            for (int ng = 0; ng < 4; ng++)
                ldm_x4t(vf[ng], vb + vb_off + kc * 16 * SQV + ng * 16);
            #pragma unroll
            for (int nt = 0; nt < 8; nt++) {
                const unsigned* bp = vf[nt >> 1];
                const int e = (nt & 1) << 1;
                mma_f16(o[nt], pa[kc][0], pa[kc][1], pa[kc][2], pa[kc][3],
                        bp[e], bp[e + 1]);
            }
        }
        __syncthreads();
    }

    #pragma unroll
    for (int s = 0; s < 2; s++) {
        const int rl = wq + gid + s * 8;
        const int e = s << 1;

        float qbk = 0.f;
        {
            const __half2* qp = (const __half2*)&sQ[rl * SQV + tig * 16];
            const float* bk = bkv + h * DH + tig * 16;
            #pragma unroll
            for (int j = 0; j < 8; j++) {
                float2 f = __half22float2(qp[j]);
                qbk += f.x * bk[2 * j] + f.y * bk[2 * j + 1];
            }
            qbk += __shfl_xor_sync(0xffffffffu, qbk, 1);
            qbk += __shfl_xor_sync(0xffffffffu, qbk, 2);
        }

        float2 raw = *(const float2*)&ls[(((size_t)b * H_ + h) * N_ + n0 + rl) * M_ + 2 * tig];
        float lg0 = scale * (raw.x + qbk);
        float lg1 = scale * (raw.y + qbk);

        float tmax = fmaxf(lg0, lg1);
        tmax = fmaxf(tmax, __shfl_xor_sync(0xffffffffu, tmax, 1));
        tmax = fmaxf(tmax, __shfl_xor_sync(0xffffffffu, tmax, 2));
        float nm = fmaxf(m_[s], tmax);
        float corr = __expf(m_[s] - nm);
        float p0 = __expf(lg0 - nm);
        float p1 = __expf(lg1 - nm);
        float ps = p0 + p1;
        ps += __shfl_xor_sync(0xffffffffu, ps, 1);
        ps += __shfl_xor_sync(0xffffffffu, ps, 2);
        float lnew = l_[s] * corr + ps;
        float inv = 1.f / lnew;

        size_t widx = (size_t)h * (B_ * N_) + bn0 + rl;
        float2 wout; wout.x = p0 * inv; wout.y = p1 * inv;
        *(float2*)&wg[widx * M_ + 2 * tig] = wout;
        if (tig == 0) asum[widx] = ps * inv;

        const float ci = corr * inv;
        __half2* op = (__half2*)&outa[(size_t)(bn0 + rl) * D_ + h * DH];
        #pragma unroll
        for (int nt = 0; nt < 8; nt++)
            op[nt * 4 + tig] = __floats2half2_rn(o[nt][e] * ci, o[nt][e + 1] * ci);
    }
}

// ---------------- launch ----------------
extern "C" void kernel_launch(void* const* d_in, const int* in_sizes, int n_in,
                              void* d_out, int out_size)
{
    const float* x   = (const float*)d_in[0];
    const float* sim = (const float*)d_in[1];
    const float* Wq  = (const float*)d_in[2];
    const float* bq  = (const float*)d_in[3];
    const float* Wkv = (const float*)d_in[4];
    const float* bkv = (const float*)d_in[5];
    const float* Wp  = (const float*)d_in[6];
    const float* bp  = (const float*)d_in[7];
    float* out = (float*)d_out;

    __half *qkv, *att, *xh, *tt, *ss, *wqkvt, *wkvh, *wpt;
    float  *ls, *wg, *asum, *bqkv;
    cudaGetSymbolAddress((void**)&qkv,   g_qkv);
    cudaGetSymbolAddress((void**)&att,   g_att);
    cudaGetSymbolAddress((void**)&xh,    g_xh);
    cudaGetSymbolAddress((void**)&tt,    g_t);
    cudaGetSymbolAddress((void**)&ss,    g_s);
    cudaGetSymbolAddress((void**)&ls,    g_ls);
    cudaGetSymbolAddress((void**)&wg,    g_w);
    cudaGetSymbolAddress((void**)&asum,  g_asum);
    cudaGetSymbolAddress((void**)&wqkvt, g_wqkvt);
    cudaGetSymbolAddress((void**)&wkvh,  g_wkvh);
    cudaGetSymbolAddress((void**)&wpt,   g_wpt);
    cudaGetSymbolAddress((void**)&bqkv,  g_bqkv);

    cudaFuncSetAttribute(attn_mma_kernel,
                         cudaFuncAttributeMaxDynamicSharedMemorySize, ATTN_SMEM_MMA);
    cudaFuncSetAttribute(hgemm_bias<float>,
                         cudaFuncAttributeMaxDynamicSharedMemorySize, GEMM_SMEM);
    cudaFuncSetAttribute(hgemm_bias<__half>,
                         cudaFuncAttributeMaxDynamicSharedMemorySize, GEMM_SMEM);
    cudaFuncSetAttribute(hgemm_svw,
                         cudaFuncAttributeMaxDynamicSharedMemorySize, SVW_SMEM);
    cudaFuncSetAttribute(hgemm_t,
                         cudaFuncAttributeMaxDynamicSharedMemorySize, TGEMM_SMEM);

    const int BN = B_ * N_;

    // 0: merged weight prep
    prep_weights<<<3465, 256>>>(Wq, Wkv, Wp, bq, bkv, wqkvt, wkvh, wpt, bqkv);
    // 1: x -> half
    f2h_kernel<<<(BN * D_ / 4 + 255) / 256, 256>>>(x, xh, BN * D_ / 4);
    // 2: merged QKV projection
    hgemm_bias<__half><<<dim3(QKVW / 128, BN / 256), 256, GEMM_SMEM>>>(
        xh, D_, 0, wqkvt, D_, 0, bqkv, qkv, QKVW, 0, D_);
    // 3: t_h = q_h @ Wk_h^T -- head-looped, double-buffered (fixed mapping)
    hgemm_t<<<dim3(D_ / 64, BN / 128), 256, TGEMM_SMEM>>>(qkv, wkvh, tt);
    // 4: raw sim logits
    logits_sim_kernel<<<BN, 256>>>(sim, tt, ls);
    // 5: flash attention
    attn_mma_kernel<<<dim3(N_ / 128, H_, B_), 256, ATTN_SMEM_MMA>>>(
        qkv, bkv, ls, att, wg, asum);
    // 6: s-pass
    spass_kernel<<<BN, 256>>>(sim, wg, ss);
    // 7: att += s_h @ Wv_h + asum*bv_h
    hgemm_svw<<<dim3(1, BN / 256, H_), 256, SVW_SMEM>>>(
        ss, wqkvt + (size_t)D_ * D_, bkv, asum, att);
    // 8: final projection
    hgemm_bias<float><<<dim3(D_ / 128, BN / 256), 256, GEMM_SMEM>>>(
        att, D_, 0, wpt, D_, 0, bp, out, D_, 0, D_);
}

// round 16
// speedup vs baseline: 1.0189x; 1.0189x over previous
#include <cuda_runtime.h>
#include <cuda_fp16.h>
#include <cstdint>
#include <cstdio>

#define B_  16
#define N_  512
#define M_  8
#define D_  768
#define H_  12
#define DH  64
#define QKVW 2304
__device__ __constant__ float kSCALE = 0.125f; // 64^{-0.5}

// ---------------- scratch ----------------
__device__ __half g_qkv  [B_ * N_ * QKVW];           // [q | k | v] half
__device__ __half g_att  [B_ * N_ * D_];             // out_self + out_sim
__device__ __half g_xh   [B_ * N_ * D_];             // x half
__device__ __half g_t    [B_ * N_ * H_ * D_];        // t[bn][h][768]
__device__ __half g_s    [H_ * B_ * N_ * D_];        // s[h][bn][768]
__device__ float  g_ls   [B_ * H_ * N_ * M_];        // raw sim logits
__device__ float  g_w    [H_ * B_ * N_ * M_];        // normalized sim weights
__device__ float  g_asum [H_ * B_ * N_];
__device__ __half g_wqkvt[QKVW * D_];                // [Wq^T ; Wkv^T]
__device__ __half g_wkvh [D_ * 2 * D_];              // Wkv row-major half
__device__ __half g_wpt  [D_ * D_];
__device__ float  g_bqkv [QKVW];                     // [bq ; bkv]

// ---------------- helpers ----------------
__device__ __forceinline__ void cp16(void* smem_dst, const void* gmem_src) {
    unsigned s = (unsigned)__cvta_generic_to_shared(smem_dst);
    asm volatile("cp.async.cg.shared.global [%0], [%1], 16;\n"
                 :: "r"(s), "l"(gmem_src));
}
#define CP_COMMIT() asm volatile("cp.async.commit_group;\n" ::: "memory")
#define CP_WAIT0()  asm volatile("cp.async.wait_group 0;\n" ::: "memory")
#define CP_WAIT2()  asm volatile("cp.async.wait_group 2;\n" ::: "memory")

__device__ __forceinline__ void mma_f16(float d[4],
                                        unsigned a0, unsigned a1, unsigned a2, unsigned a3,
                                        unsigned b0, unsigned b1)
{
    asm volatile(
        "mma.sync.aligned.m16n8k16.row.col.f32.f16.f16.f32 "
        "{%0,%1,%2,%3}, {%4,%5,%6,%7}, {%8,%9}, {%0,%1,%2,%3};\n"
        : "+f"(d[0]), "+f"(d[1]), "+f"(d[2]), "+f"(d[3])
        : "r"(a0), "r"(a1), "r"(a2), "r"(a3), "r"(b0), "r"(b1));
}
__device__ __forceinline__ void ldm_x4(unsigned r[4], const __half* p) {
    unsigned a = (unsigned)__cvta_generic_to_shared(p);
    asm volatile("ldmatrix.sync.aligned.m8n8.x4.shared.b16 {%0,%1,%2,%3}, [%4];"
                 : "=r"(r[0]), "=r"(r[1]), "=r"(r[2]), "=r"(r[3]) : "r"(a));
}
__device__ __forceinline__ void ldm_x4t(unsigned r[4], const __half* p) {
    unsigned a = (unsigned)__cvta_generic_to_shared(p);
    asm volatile("ldmatrix.sync.aligned.m8n8.x4.trans.shared.b16 {%0,%1,%2,%3}, [%4];"
                 : "=r"(r[0]), "=r"(r[1]), "=r"(r[2]), "=r"(r[3]) : "r"(a));
}
__device__ __forceinline__ unsigned packh2(float x, float y) {
    __half2 t = __floats2half2_rn(x, y);
    return *(unsigned*)&t;
}

// ---------------- merged prep kernel ----------------
__global__ __launch_bounds__(256) void prep_weights(
    const float* __restrict__ Wq, const float* __restrict__ Wkv,
    const float* __restrict__ Wp,
    const float* __restrict__ bq, const float* __restrict__ bkv,
    __half* __restrict__ wqkvt, __half* __restrict__ wkvh,
    __half* __restrict__ wpt, float* __restrict__ bqkv)
{
    __shared__ float t[32][33];
    const int bid = blockIdx.x;
    const int tid = threadIdx.x;

    if (bid < 2304) {
        const float* W; __half* Wt; int K, Nn, bx, by;
        if (bid < 576)       { W = Wq;  Wt = wqkvt;                K = D_; Nn = D_;     bx = bid % 24;          by = bid / 24; }
        else if (bid < 1728) { W = Wkv; Wt = wqkvt + (size_t)D_ * D_; K = D_; Nn = 2 * D_; bx = (bid - 576) % 48;  by = (bid - 576) / 48; }
        else                 { W = Wp;  Wt = wpt;                  K = D_; Nn = D_;     bx = (bid - 1728) % 24; by = (bid - 1728) / 24; }
        const int k0 = by * 32, n0 = bx * 32;
        const int x = tid & 31, y = tid >> 5;
        #pragma unroll
        for (int i = 0; i < 32; i += 8)
            t[y + i][x] = W[(size_t)(k0 + y + i) * Nn + n0 + x];
        __syncthreads();
        #pragma unroll
        for (int i = 0; i < 32; i += 8)
            Wt[(size_t)(n0 + y + i) * K + k0 + x] = __float2half_rn(t[x][y + i]);
    } else if (bid < 3456) {
        int i = (bid - 2304) * 256 + tid;
        if (i < D_ * 2 * D_ / 4) {
            float4 v = ((const float4*)Wkv)[i];
            ((__half2*)wkvh)[2 * i]     = __floats2half2_rn(v.x, v.y);
            ((__half2*)wkvh)[2 * i + 1] = __floats2half2_rn(v.z, v.w);
        }
    } else {
        int i = (bid - 3456) * 256 + tid;
        if (i < D_) bqkv[i] = bq[i];
        else if (i < QKVW) bqkv[i] = bkv[i - D_];
    }
}

__global__ void f2h_kernel(const float* __restrict__ in,
                           __half* __restrict__ out, int n4) {
    int i = blockIdx.x * blockDim.x + threadIdx.x;
    if (i < n4) {
        float4 v = ((const float4*)in)[i];
        ((__half2*)out)[2 * i]     = __floats2half2_rn(v.x, v.y);
        ((__half2*)out)[2 * i + 1] = __floats2half2_rn(v.z, v.w);
    }
}

// ---------------- generalized fp16 GEMM + bias (256x128 tile, ldmatrix) ---------
#define SAH  40
#define ABYT (256 * SAH * 2)
#define BBYT (128 * SAH * 2)
#define STG  (ABYT + BBYT)
#define GEMM_SMEM (3 * STG)

template <typename OutT>
__global__ __launch_bounds__(256, 1) void hgemm_bias(
    const __half* __restrict__ A, int lda, long zA,
    const __half* __restrict__ Bt, int ldb, long zB,
    const float* __restrict__ bias,
    OutT* __restrict__ C, int ldc, long zC,
    int Kdim)
{
    extern __shared__ __half smem[];
    A  += (size_t)blockIdx.z * zA;
    Bt += (size_t)blockIdx.z * zB;
    C  += (size_t)blockIdx.z * zC;

    const int tid  = threadIdx.x;
    const int warp = tid >> 5;
    const int lane = tid & 31;
    const int gid  = lane >> 2;
    const int tig  = lane & 3;
    const int wm   = (warp >> 1) * 64;
    const int wn   = (warp & 1)  * 64;
    const int bm   = blockIdx.y * 256;
    const int bn   = blockIdx.x * 128;

    const int crow = tid >> 2;
    const int cg   = (tid & 3) << 3;
    const __half* Agp = A  + (size_t)(bm + crow) * lda + cg;
    const __half* Bgp = Bt + (size_t)(bn + crow) * ldb + cg;
    const size_t a64 = (size_t)64 * lda;
    const size_t b64 = (size_t)64 * ldb;

    const int ktiles = Kdim >> 5;

    auto load_stage = [&](int s, int t) {
        __half* as = smem + s * (STG / 2);
        __half* bs = as + ABYT / 2;
        const int k0 = t << 5;
        #pragma unroll
        for (int i = 0; i < 4; i++)
            cp16(&as[(crow + i * 64) * SAH + cg], Agp + i * a64 + k0);
        #pragma unroll
        for (int i = 0; i < 2; i++)
            cp16(&bs[(crow + i * 64) * SAH + cg], Bgp + i * b64 + k0);
    };

    float acc[4][8][4];
    #pragma unroll
    for (int mt = 0; mt < 4; mt++)
        #pragma unroll
        for (int nt = 0; nt < 8; nt++)
            #pragma unroll
            for (int c = 0; c < 4; c++) acc[mt][nt][c] = 0.f;

    load_stage(0, 0); CP_COMMIT();
    if (ktiles > 1) load_stage(1, 1);
    CP_COMMIT();

    const int a_off = (wm + (lane & 15)) * SAH + ((lane >> 4) << 3);
    const int b_off = (wn + ((lane >> 4) << 3) + (lane & 7)) * SAH
                    + (((lane >> 3) & 1) << 3);

    for (int t = 0; t < ktiles; t++) {
        if (t + 2 < ktiles) load_stage((t + 2) % 3, t + 2);
        CP_COMMIT();
        CP_WAIT2();
        __syncthreads();

        const __half* as = smem + (t % 3) * (STG / 2);
        const __half* bs = as + ABYT / 2;
        #pragma unroll
        for (int ks = 0; ks < 2; ks++) {
            const int kh = ks << 4;
            unsigned afr[4][4], bfr[4][4];
            #pragma unroll
            for (int mt = 0; mt < 4; mt++)
                ldm_x4(afr[mt], as + a_off + mt * 16 * SAH + kh);
            #pragma unroll
            for (int np = 0; np < 4; np++)
                ldm_x4(bfr[np], bs + b_off + np * 16 * SAH + kh);
            #pragma unroll
            for (int mt = 0; mt < 4; mt++)
                #pragma unroll
                for (int nt = 0; nt < 8; nt++) {
                    const unsigned* bp = bfr[nt >> 1];
                    const int e = (nt & 1) << 1;
                    mma_f16(acc[mt][nt],
                            afr[mt][0], afr[mt][1], afr[mt][2], afr[mt][3],
                            bp[e], bp[e + 1]);
                }
        }
        __syncthreads();
    }

    #pragma unroll
    for (int mt = 0; mt < 4; mt++) {
        const int row0 = bm + wm + mt * 16 + gid;
        #pragma unroll
        for (int nt = 0; nt < 8; nt++) {
            const int col = bn + wn + nt * 8 + 2 * tig;
            const float b0 = bias[col], b1 = bias[col + 1];
            if constexpr (sizeof(OutT) == 4) {
                float2 o0, o1;
                o0.x = acc[mt][nt][0] + b0; o0.y = acc[mt][nt][1] + b1;
                o1.x = acc[mt][nt][2] + b0; o1.y = acc[mt][nt][3] + b1;
                *(float2*)&C[(size_t)row0 * ldc + col]       = o0;
                *(float2*)&C[(size_t)(row0 + 8) * ldc + col] = o1;
            } else {
                *(__half2*)&C[(size_t)row0 * ldc + col] =
                    __floats2half2_rn(acc[mt][nt][0] + b0, acc[mt][nt][1] + b1);
                *(__half2*)&C[(size_t)(row0 + 8) * ldc + col] =
                    __floats2half2_rn(acc[mt][nt][2] + b0, acc[mt][nt][3] + b1);
            }
        }
    }
}

// ---------------- dedicated t-GEMM (round-12 measured-best version) -------------
// 128x64 tile, K=64 single-shot, 8 warps (4m x 2n), warp tile 32x32, 3 CTAs/SM.
#define TST 72
__global__ __launch_bounds__(256, 3) void hgemm_t(
    const __half* __restrict__ qkv,    // A: lda=QKVW, head offset z*64
    const __half* __restrict__ wkvh,   // B: ldb=1536, head offset z*64
    __half* __restrict__ tt)           // C: ldc=H_*D_, head offset z*768
{
    __shared__ __half sA[128 * TST];
    __shared__ __half sB[64 * TST];

    const int tid  = threadIdx.x;
    const int warp = tid >> 5;
    const int lane = tid & 31;
    const int gid  = lane >> 2;
    const int tig  = lane & 3;
    const int wm   = (warp >> 1) * 32;   // 0,32,64,96
    const int wn   = (warp & 1)  * 32;   // 0,32
    const int bm   = blockIdx.y * 128;
    const int bn   = blockIdx.x * 64;
    const int z    = blockIdx.z;

    // load A: 1024 granules (128 rows x 8), 4 per thread
    #pragma unroll
    for (int i = 0; i < 4; i++) {
        const int idx = tid + i * 256;
        const int row = idx >> 3, g = (idx & 7) << 3;
        cp16(&sA[row * TST + g],
             qkv + (size_t)(bm + row) * QKVW + z * DH + g);
    }
    // load B: 512 granules (64 rows x 8), 2 per thread
    #pragma unroll
    for (int i = 0; i < 2; i++) {
        const int idx = tid + i * 256;
        const int row = idx >> 3, g = (idx & 7) << 3;
        cp16(&sB[row * TST + g],
             wkvh + (size_t)(bn + row) * (2 * D_) + z * DH + g);
    }
    CP_COMMIT();
    CP_WAIT0();
    __syncthreads();

    float acc[2][4][4];
    #pragma unroll
    for (int mt = 0; mt < 2; mt++)
        #pragma unroll
        for (int nt = 0; nt < 4; nt++)
            #pragma unroll
            for (int c = 0; c < 4; c++) acc[mt][nt][c] = 0.f;

    const int a_off = (wm + (lane & 15)) * TST + ((lane >> 4) << 3);
    const int b_off = (wn + ((lane >> 4) << 3) + (lane & 7)) * TST
                    + (((lane >> 3) & 1) << 3);

    #pragma unroll
    for (int ks = 0; ks < 4; ks++) {
        const int kh = ks << 4;
        unsigned afr[2][4], bfr[2][4];
        #pragma unroll
        for (int mt = 0; mt < 2; mt++)
            ldm_x4(afr[mt], sA + a_off + mt * 16 * TST + kh);
        #pragma unroll
        for (int ng = 0; ng < 2; ng++)
            ldm_x4(bfr[ng], sB + b_off + ng * 16 * TST + kh);
        #pragma unroll
        for (int mt = 0; mt < 2; mt++)
            #pragma unroll
            for (int nt = 0; nt < 4; nt++) {
                const unsigned* bp = bfr[nt >> 1];
                const int e = (nt & 1) << 1;
                mma_f16(acc[mt][nt],
                        afr[mt][0], afr[mt][1], afr[mt][2], afr[mt][3],
                        bp[e], bp[e + 1]);
            }
    }

    // store (no bias): tt row-major per head
    __half* C = tt + (size_t)z * D_;
    #pragma unroll
    for (int mt = 0; mt < 2; mt++) {
        const int row0 = bm + wm + mt * 16 + gid;
        #pragma unroll
        for (int nt = 0; nt < 4; nt++) {
            const int col = bn + wn + nt * 8 + 2 * tig;
            *(__half2*)&C[(size_t)row0 * (H_ * D_) + col] =
                __floats2half2_rn(acc[mt][nt][0], acc[mt][nt][1]);
            *(__half2*)&C[(size_t)(row0 + 8) * (H_ * D_) + col] =
                __floats2half2_rn(acc[mt][nt][2], acc[mt][nt][3]);
        }
    }
}

// ---------------- svw GEMM ----------------
#define SVW_ABYT (256 * SAH * 2)
#define SVW_BBYT (64 * SAH * 2)
#define SVW_STG  (SVW_ABYT + SVW_BBYT)
#define SVW_SMEM (3 * SVW_STG)

__global__ __launch_bounds__(256, 1) void hgemm_svw(
    const __half* __restrict__ S,
    const __half* __restrict__ Wkvt,
    const float* __restrict__ bkv,
    const float* __restrict__ asum,
    __half* __restrict__ att)
{
    extern __shared__ __half smem[];
    const int h = blockIdx.z;
    const __half* A  = S + (size_t)h * (B_ * N_) * D_;
    const __half* Bt = Wkvt + (size_t)(D_ + h * DH) * D_;
    const float* bv  = bkv + D_ + h * DH;
    const float* ash = asum + (size_t)h * (B_ * N_);

    const int tid  = threadIdx.x;
    const int warp = tid >> 5;
    const int lane = tid & 31;
    const int gid  = lane >> 2;
    const int tig  = lane & 3;
    const int wm   = warp * 32;
    const int bm   = blockIdx.y * 256;

    const int crow = tid >> 2;
    const int cg   = (tid & 3) << 3;
    const __half* Agp = A  + (size_t)(bm + crow) * D_ + cg;
    const __half* Bgp = Bt + (size_t)crow * D_ + cg;
    const size_t a64 = (size_t)64 * D_;

    const int ktiles = D_ >> 5;

    auto load_stage = [&](int s, int t) {
        __half* as = smem + s * (SVW_STG / 2);
        __half* bs = as + SVW_ABYT / 2;
        const int k0 = t << 5;
        #pragma unroll
        for (int i = 0; i < 4; i++)
            cp16(&as[(crow + i * 64) * SAH + cg], Agp + i * a64 + k0);
        cp16(&bs[crow * SAH + cg], Bgp + k0);
    };

    float acc[2][8][4];
    #pragma unroll
    for (int mt = 0; mt < 2; mt++)
        #pragma unroll
        for (int nt = 0; nt < 8; nt++)
            #pragma unroll
            for (int c = 0; c < 4; c++) acc[mt][nt][c] = 0.f;

    load_stage(0, 0); CP_COMMIT();
    load_stage(1, 1); CP_COMMIT();

    const int a_off = (wm + (lane & 15)) * SAH + ((lane >> 4) << 3);
    const int b_off = (((lane >> 4) << 3) + (lane & 7)) * SAH
                    + (((lane >> 3) & 1) << 3);

    for (int t = 0; t < ktiles; t++) {
        if (t + 2 < ktiles) load_stage((t + 2) % 3, t + 2);
        CP_COMMIT();
        CP_WAIT2();
        __syncthreads();

        const __half* as = smem + (t % 3) * (SVW_STG / 2);
        const __half* bs = as + SVW_ABYT / 2;
        #pragma unroll
        for (int ks = 0; ks < 2; ks++) {
            const int kh = ks << 4;
            unsigned afr[2][4], bfr[4][4];
            #pragma unroll
            for (int mt = 0; mt < 2; mt++)
                ldm_x4(afr[mt], as + a_off + mt * 16 * SAH + kh);
            #pragma unroll
            for (int np = 0; np < 4; np++)
                ldm_x4(bfr[np], bs + b_off + np * 16 * SAH + kh);
            #pragma unroll
            for (int mt = 0; mt < 2; mt++)
                #pragma unroll
                for (int nt = 0; nt < 8; nt++) {
                    const unsigned* bp = bfr[nt >> 1];
                    const int e = (nt & 1) << 1;
                    mma_f16(acc[mt][nt],
                            afr[mt][0], afr[mt][1], afr[mt][2], afr[mt][3],
                            bp[e], bp[e + 1]);
                }
        }
        __syncthreads();
    }

    #pragma unroll
    for (int mt = 0; mt < 2; mt++) {
        const int row0 = bm + wm + mt * 16 + gid;
        const float as0 = ash[row0], as1 = ash[row0 + 8];
        #pragma unroll
        for (int nt = 0; nt < 8; nt++) {
            const int col = nt * 8 + 2 * tig;
            const float b0 = bv[col], b1 = bv[col + 1];
            __half2* c0 = (__half2*)&att[(size_t)row0 * D_ + h * DH + col];
            __half2* c1 = (__half2*)&att[(size_t)(row0 + 8) * D_ + h * DH + col];
            float2 p0 = __half22float2(*c0);
            float2 p1 = __half22float2(*c1);
            *c0 = __floats2half2_rn(acc[mt][nt][0] + as0 * b0 + p0.x,
                                    acc[mt][nt][1] + as0 * b1 + p0.y);
            *c1 = __floats2half2_rn(acc[mt][nt][2] + as1 * b0 + p1.x,
                                    acc[mt][nt][3] + as1 * b1 + p1.y);
        }
    }
}

// ---------------- sim logits (fp32 sim input) ----------------
__global__ __launch_bounds__(256) void logits_sim_kernel(
    const float* __restrict__ sim,
    const __half* __restrict__ t,
    float* __restrict__ ls)
{
    __shared__ float  ssim[M_ * D_];
    __shared__ __half st[H_ * D_];
    const int bn = blockIdx.x;
    const int tid = threadIdx.x;
    const float4* sg = (const float4*)(sim + (size_t)bn * M_ * D_);
    float4* sd = (float4*)ssim;
    for (int i = tid; i < M_ * D_ / 4; i += 256) sd[i] = sg[i];
    const float4* tg = (const float4*)(t + (size_t)bn * H_ * D_);
    float4* td = (float4*)st;
    for (int i = tid; i < H_ * D_ / 8; i += 256) td[i] = tg[i];
    __syncthreads();

    const int warp = tid >> 5, lane = tid & 31;
    const int b = bn >> 9, n = bn & 511;
    const float2* s2 = (const float2*)ssim;
    const __half2* t2 = (const __half2*)st;
    for (int d = warp; d < H_ * M_; d += 8) {
        const int h = d >> 3, m = d & 7;
        float a = 0.f;
        #pragma unroll
        for (int j = 0; j < 12; j++) {
            float2 x = s2[m * 384 + lane + 32 * j];
            float2 y = __half22float2(t2[h * 384 + lane + 32 * j]);
            a += x.x * y.x + x.y * y.y;
        }
        #pragma unroll
        for (int o = 16; o; o >>= 1) a += __shfl_xor_sync(0xffffffffu, a, o);
        if (lane == 0)
            ls[(((size_t)b * H_ + h) * N_ + n) * M_ + m] = a;
    }
}

// ---------------- s-pass (fp32 sim input) ----------------
__global__ __launch_bounds__(256) void spass_kernel(
    const float* __restrict__ sim,
    const float* __restrict__ w,
    __half* __restrict__ s)
{
    __shared__ float ssim[M_ * D_];
    __shared__ float sw[H_ * M_];
    const int bn = blockIdx.x;
    const int tid = threadIdx.x;
    const float4* sg = (const float4*)(sim + (size_t)bn * M_ * D_);
    float4* sd = (float4*)ssim;
    for (int i = tid; i < M_ * D_ / 4; i += 256) sd[i] = sg[i];
    if (tid < H_ * M_) {
        int h = tid >> 3, m = tid & 7;
        sw[tid] = w[((size_t)h * (B_ * N_) + bn) * M_ + m];
    }
    __syncthreads();

    const float2* s2 = (const float2*)ssim;
    for (int idx = tid; idx < H_ * 384; idx += 256) {
        const int h = idx / 384, c2 = idx % 384;
        float ax = 0.f, ay = 0.f;
        #pragma unroll
        for (int m = 0; m < M_; m++) {
            float2 v = s2[m * 384 + c2];
            float wm_ = sw[h * M_ + m];
            ax += wm_ * v.x; ay += wm_ * v.y;
        }
        ((__half2*)s)[((size_t)h * (B_ * N_) + bn) * 384 + c2] =
            __floats2half2_rn(ax, ay);
    }
}

// ---------------- tensor-core flash attention (128 queries, 8 warps) ----------
#define SQV 72
#define QSZ (128 * SQV)
#define TSZ (64 * SQV)
#define ATTN_SMEM_MMA ((QSZ + 6 * TSZ) * 2)   // 73728 B

__global__ __launch_bounds__(256, 2) void attn_mma_kernel(
    const __half* __restrict__ qkv,
    const float*  __restrict__ bkv,
    const float*  __restrict__ ls,
    __half* __restrict__ outa,
    float* __restrict__ wg,
    float* __restrict__ asum)
{
    extern __shared__ __half smh[];
    __half* sQ = smh;
    __half* sK = sQ + QSZ;
    __half* sV = sK + 3 * TSZ;

    const int tid = threadIdx.x;
    const int warp = tid >> 5, lane = tid & 31;
    const int gid = lane >> 2, tig = lane & 3;
    const int n0 = blockIdx.x * 128, h = blockIdx.y, b = blockIdx.z;
    const int wq = warp * 16;
    const float scale = kSCALE;
    const int bn0 = b * N_ + n0;

    {
        const int row = tid >> 1, g0 = (tid & 1) << 5;
        const __half* src = qkv + (size_t)(bn0 + row) * QKVW + h * DH + g0;
        #pragma unroll
        for (int i = 0; i < 4; i++)
            cp16(&sQ[row * SQV + g0 + i * 8], src + i * 8);
    }
    auto load_tile = [&](int st, int kt) {
        const int row = tid >> 2, g = (tid & 3) << 4;
        size_t go = (size_t)(b * N_ + kt * 64 + row) * QKVW + D_ + h * DH + g;
        cp16(&sK[st * TSZ + row * SQV + g],     qkv + go);
        cp16(&sK[st * TSZ + row * SQV + g + 8], qkv + go + 8);
        cp16(&sV[st * TSZ + row * SQV + g],     qkv + go + D_);
        cp16(&sV[st * TSZ + row * SQV + g + 8], qkv + go + D_ + 8);
    };
    load_tile(0, 0); CP_COMMIT();
    load_tile(1, 1); CP_COMMIT();

    float m_[2] = {-1e30f, -1e30f}, l_[2] = {0.f, 0.f};
    float o[8][4];
    #pragma unroll
    for (int nt = 0; nt < 8; nt++)
        #pragma unroll
        for (int c = 0; c < 4; c++) o[nt][c] = 0.f;

    unsigned qa[4][4];
    const int a_off = (wq + (lane & 15)) * SQV + ((lane >> 4) << 3);
    const int kb_off = (((lane >> 4) << 3) + (lane & 7)) * SQV
                     + (((lane >> 3) & 1) << 3);
    const int vb_off = (((lane >> 3) & 1) * 8 + (lane & 7)) * SQV
                     + ((lane >> 4) << 3);
    bool qloaded = false;

    for (int kt = 0; kt < 8; kt++) {
        if (kt + 2 < 8) load_tile((kt + 2) % 3, kt + 2);
        CP_COMMIT();
        CP_WAIT2();
        __syncthreads();

        if (!qloaded) {
            #pragma unroll
            for (int ks = 0; ks < 4; ks++)
                ldm_x4(qa[ks], sQ + a_off + ks * 16);
            qloaded = true;
        }

        const __half* kb = sK + (kt % 3) * TSZ;
        const __half* vb = sV + (kt % 3) * TSZ;

        float sc[8][4];
        #pragma unroll
        for (int nt = 0; nt < 8; nt++)
            #pragma unroll
            for (int c = 0; c < 4; c++) sc[nt][c] = 0.f;
        #pragma unroll
        for (int ks = 0; ks < 4; ks++) {
            unsigned kf[4][4];
            #pragma unroll
            for (int ng = 0; ng < 4; ng++)
                ldm_x4(kf[ng], kb + kb_off + ng * 16 * SQV + ks * 16);
            #pragma unroll
            for (int nt = 0; nt < 8; nt++) {
                const unsigned* bp = kf[nt >> 1];
                const int e = (nt & 1) << 1;
                mma_f16(sc[nt], qa[ks][0], qa[ks][1], qa[ks][2], qa[ks][3],
                        bp[e], bp[e + 1]);
            }
        }
        #pragma unroll
        for (int nt = 0; nt < 8; nt++)
            #pragma unroll
            for (int c = 0; c < 4; c++) sc[nt][c] *= scale;

        #pragma unroll
        for (int s = 0; s < 2; s++) {
            const int e = s << 1;
            float tmax = -1e30f;
            #pragma unroll
            for (int nt = 0; nt < 8; nt++)
                tmax = fmaxf(tmax, fmaxf(sc[nt][e], sc[nt][e + 1]));
            tmax = fmaxf(tmax, __shfl_xor_sync(0xffffffffu, tmax, 1));
            tmax = fmaxf(tmax, __shfl_xor_sync(0xffffffffu, tmax, 2));
            float nm = fmaxf(m_[s], tmax);
            float corr = __expf(m_[s] - nm);
            float sum = 0.f;
            #pragma unroll
            for (int nt = 0; nt < 8; nt++) {
                sc[nt][e]     = __expf(sc[nt][e] - nm);
                sc[nt][e + 1] = __expf(sc[nt][e + 1] - nm);
                sum += sc[nt][e] + sc[nt][e + 1];
            }
            sum += __shfl_xor_sync(0xffffffffu, sum, 1);
            sum += __shfl_xor_sync(0xffffffffu, sum, 2);
            l_[s] = l_[s] * corr + sum;
            m_[s] = nm;
            #pragma unroll
            for (int nt = 0; nt < 8; nt++) {
                o[nt][e]     *= corr;
                o[nt][e + 1] *= corr;
            }
        }

        unsigned pa[4][4];
        #pragma unroll
        for (int kc = 0; kc < 4; kc++) {
            pa[kc][0] = packh2(sc[2 * kc][0],     sc[2 * kc][1]);
            pa[kc][1] = packh2(sc[2 * kc][2],     sc[2 * kc][3]);
            pa[kc][2] = packh2(sc[2 * kc + 1][0], sc[2 * kc + 1][1]);
            pa[kc][3] = packh2(sc[2 * kc + 1][2], sc[2 * kc + 1][3]);
        }

        #pragma unroll
        for (int kc = 0; kc < 4; kc++) {
            unsigned vf[4][4];
            #pragma unroll
            for (int ng = 0; ng < 4; ng++)
                ldm_x4t(vf[ng], vb + vb_off + kc * 16 * SQV + ng * 16);
            #pragma unroll
            for (int nt = 0; nt < 8; nt++) {
                const unsigned* bp = vf[nt >> 1];
                const int e = (nt & 1) << 1;
                mma_f16(o[nt], pa[kc][0], pa[kc][1], pa[kc][2], pa[kc][3],
                        bp[e], bp[e + 1]);
            }
        }
        __syncthreads();
    }

    #pragma unroll
    for (int s = 0; s < 2; s++) {
        const int rl = wq + gid + s * 8;
        const int e = s << 1;

        float qbk = 0.f;
        {
            const __half2* qp = (const __half2*)&sQ[rl * SQV + tig * 16];
            const float* bk = bkv + h * DH + tig * 16;
            #pragma unroll
            for (int j = 0; j < 8; j++) {
                float2 f = __half22float2(qp[j]);
                qbk += f.x * bk[2 * j] + f.y * bk[2 * j + 1];
            }
            qbk += __shfl_xor_sync(0xffffffffu, qbk, 1);
            qbk += __shfl_xor_sync(0xffffffffu, qbk, 2);
        }

        float2 raw = *(const float2*)&ls[(((size_t)b * H_ + h) * N_ + n0 + rl) * M_ + 2 * tig];
        float lg0 = scale * (raw.x + qbk);
        float lg1 = scale * (raw.y + qbk);

        float tmax = fmaxf(lg0, lg1);
        tmax = fmaxf(tmax, __shfl_xor_sync(0xffffffffu, tmax, 1));
        tmax = fmaxf(tmax, __shfl_xor_sync(0xffffffffu, tmax, 2));
        float nm = fmaxf(m_[s], tmax);
        float corr = __expf(m_[s] - nm);
        float p0 = __expf(lg0 - nm);
        float p1 = __expf(lg1 - nm);
        float ps = p0 + p1;
        ps += __shfl_xor_sync(0xffffffffu, ps, 1);
        ps += __shfl_xor_sync(0xffffffffu, ps, 2);
        float lnew = l_[s] * corr + ps;
        float inv = 1.f / lnew;

        size_t widx = (size_t)h * (B_ * N_) + bn0 + rl;
        float2 wout; wout.x = p0 * inv; wout.y = p1 * inv;
        *(float2*)&wg[widx * M_ + 2 * tig] = wout;
        if (tig == 0) asum[widx] = ps * inv;

        const float ci = corr * inv;
        __half2* op = (__half2*)&outa[(size_t)(bn0 + rl) * D_ + h * DH];
        #pragma unroll
        for (int nt = 0; nt < 8; nt++)
            op[nt * 4 + tig] = __floats2half2_rn(o[nt][e] * ci, o[nt][e + 1] * ci);
    }
}

// ---------------- launch ----------------
extern "C" void kernel_launch(void* const* d_in, const int* in_sizes, int n_in,
                              void* d_out, int out_size)
{
    const float* x   = (const float*)d_in[0];
    const float* sim = (const float*)d_in[1];
    const float* Wq  = (const float*)d_in[2];
    const float* bq  = (const float*)d_in[3];
    const float* Wkv = (const float*)d_in[4];
    const float* bkv = (const float*)d_in[5];
    const float* Wp  = (const float*)d_in[6];
    const float* bp  = (const float*)d_in[7];
    float* out = (float*)d_out;

    __half *qkv, *att, *xh, *tt, *ss, *wqkvt, *wkvh, *wpt;
    float  *ls, *wg, *asum, *bqkv;
    cudaGetSymbolAddress((void**)&qkv,   g_qkv);
    cudaGetSymbolAddress((void**)&att,   g_att);
    cudaGetSymbolAddress((void**)&xh,    g_xh);
    cudaGetSymbolAddress((void**)&tt,    g_t);
    cudaGetSymbolAddress((void**)&ss,    g_s);
    cudaGetSymbolAddress((void**)&ls,    g_ls);
    cudaGetSymbolAddress((void**)&wg,    g_w);
    cudaGetSymbolAddress((void**)&asum,  g_asum);
    cudaGetSymbolAddress((void**)&wqkvt, g_wqkvt);
    cudaGetSymbolAddress((void**)&wkvh,  g_wkvh);
    cudaGetSymbolAddress((void**)&wpt,   g_wpt);
    cudaGetSymbolAddress((void**)&bqkv,  g_bqkv);

    cudaFuncSetAttribute(attn_mma_kernel,
                         cudaFuncAttributeMaxDynamicSharedMemorySize, ATTN_SMEM_MMA);
    cudaFuncSetAttribute(hgemm_bias<float>,
                         cudaFuncAttributeMaxDynamicSharedMemorySize, GEMM_SMEM);
    cudaFuncSetAttribute(hgemm_bias<__half>,
                         cudaFuncAttributeMaxDynamicSharedMemorySize, GEMM_SMEM);
    cudaFuncSetAttribute(hgemm_svw,
                         cudaFuncAttributeMaxDynamicSharedMemorySize, SVW_SMEM);

    const int BN = B_ * N_;

    // 0: merged weight prep
    prep_weights<<<3465, 256>>>(Wq, Wkv, Wp, bq, bkv, wqkvt, wkvh, wpt, bqkv);
    // 1: x -> half
    f2h_kernel<<<(BN * D_ / 4 + 255) / 256, 256>>>(x, xh, BN * D_ / 4);
    // 2: merged QKV projection
    hgemm_bias<__half><<<dim3(QKVW / 128, BN / 256), 256, GEMM_SMEM>>>(
        xh, D_, 0, wqkvt, D_, 0, bqkv, qkv, QKVW, 0, D_);
    // 3: t_h = q_h @ Wk_h^T -- round-12 measured-best config
    hgemm_t<<<dim3(D_ / 64, BN / 128, H_), 256>>>(qkv, wkvh, tt);
    // 4: raw sim logits
    logits_sim_kernel<<<BN, 256>>>(sim, tt, ls);
    // 5: flash attention
    attn_mma_kernel<<<dim3(N_ / 128, H_, B_), 256, ATTN_SMEM_MMA>>>(
        qkv, bkv, ls, att, wg, asum);
    // 6: s-pass
    spass_kernel<<<BN, 256>>>(sim, wg, ss);
    // 7: att += s_h @ Wv_h + asum*bv_h
    hgemm_svw<<<dim3(1, BN / 256, H_), 256, SVW_SMEM>>>(
        ss, wqkvt + (size_t)D_ * D_, bkv, asum, att);
    // 8: final projection
    hgemm_bias<float><<<dim3(D_ / 128, BN / 256), 256, GEMM_SMEM>>>(
        att, D_, 0, wpt, D_, 0, bp, out, D_, 0, D_);
}

// round 17
// speedup vs baseline: 1.0296x; 1.0105x over previous
#include <cuda_runtime.h>
#include <cuda_fp16.h>
#include <cstdint>
#include <cstdio>

#define B_  16
#define N_  512
#define M_  8
#define D_  768
#define H_  12
#define DH  64
#define QKVW 2304
__device__ __constant__ float kSCALE = 0.125f; // 64^{-0.5}

// ---------------- scratch ----------------
__device__ __half g_qkv  [B_ * N_ * QKVW];           // [q | k | v] half
__device__ __half g_att  [B_ * N_ * D_];             // out_self + out_sim
__device__ __half g_xh   [B_ * N_ * D_];             // x half
__device__ __half g_t    [B_ * N_ * H_ * D_];        // t[bn][h][768]
__device__ __half g_s    [H_ * B_ * N_ * D_];        // s[h][bn][768]
__device__ float  g_ls   [B_ * H_ * N_ * M_];        // raw sim logits
__device__ float  g_w    [H_ * B_ * N_ * M_];        // normalized sim weights
__device__ float  g_asum [H_ * B_ * N_];
__device__ __half g_wqkvt[QKVW * D_];                // [Wq^T ; Wkv^T]
__device__ __half g_wkvh [D_ * 2 * D_];              // Wkv row-major half
__device__ __half g_wpt  [D_ * D_];
__device__ float  g_bqkv [QKVW];                     // [bq ; bkv]

// ---------------- helpers ----------------
__device__ __forceinline__ void cp16(void* smem_dst, const void* gmem_src) {
    unsigned s = (unsigned)__cvta_generic_to_shared(smem_dst);
    asm volatile("cp.async.cg.shared.global [%0], [%1], 16;\n"
                 :: "r"(s), "l"(gmem_src));
}
#define CP_COMMIT() asm volatile("cp.async.commit_group;\n" ::: "memory")
#define CP_WAIT0()  asm volatile("cp.async.wait_group 0;\n" ::: "memory")
#define CP_WAIT2()  asm volatile("cp.async.wait_group 2;\n" ::: "memory")

__device__ __forceinline__ void mma_f16(float d[4],
                                        unsigned a0, unsigned a1, unsigned a2, unsigned a3,
                                        unsigned b0, unsigned b1)
{
    asm volatile(
        "mma.sync.aligned.m16n8k16.row.col.f32.f16.f16.f32 "
        "{%0,%1,%2,%3}, {%4,%5,%6,%7}, {%8,%9}, {%0,%1,%2,%3};\n"
        : "+f"(d[0]), "+f"(d[1]), "+f"(d[2]), "+f"(d[3])
        : "r"(a0), "r"(a1), "r"(a2), "r"(a3), "r"(b0), "r"(b1));
}
__device__ __forceinline__ void ldm_x4(unsigned r[4], const __half* p) {
    unsigned a = (unsigned)__cvta_generic_to_shared(p);
    asm volatile("ldmatrix.sync.aligned.m8n8.x4.shared.b16 {%0,%1,%2,%3}, [%4];"
                 : "=r"(r[0]), "=r"(r[1]), "=r"(r[2]), "=r"(r[3]) : "r"(a));
}
__device__ __forceinline__ void ldm_x4t(unsigned r[4], const __half* p) {
    unsigned a = (unsigned)__cvta_generic_to_shared(p);
    asm volatile("ldmatrix.sync.aligned.m8n8.x4.trans.shared.b16 {%0,%1,%2,%3}, [%4];"
                 : "=r"(r[0]), "=r"(r[1]), "=r"(r[2]), "=r"(r[3]) : "r"(a));
}
__device__ __forceinline__ unsigned packh2(float x, float y) {
    __half2 t = __floats2half2_rn(x, y);
    return *(unsigned*)&t;
}

// ---------------- merged prep kernel (weights + x f2h + biases) ----------------
// blockIdx ranges: [0,2304) transposes | [2304,3456) f2h(Wkv) | [3456,3465) bias
//                  [3465,9609) f2h(x)
__global__ __launch_bounds__(256) void prep_weights(
    const float* __restrict__ Wq, const float* __restrict__ Wkv,
    const float* __restrict__ Wp, const float* __restrict__ x,
    const float* __restrict__ bq, const float* __restrict__ bkv,
    __half* __restrict__ wqkvt, __half* __restrict__ wkvh,
    __half* __restrict__ wpt, __half* __restrict__ xh,
    float* __restrict__ bqkv)
{
    __shared__ float t[32][33];
    const int bid = blockIdx.x;
    const int tid = threadIdx.x;

    if (bid < 2304) {
        const float* W; __half* Wt; int K, Nn, bx, by;
        if (bid < 576)       { W = Wq;  Wt = wqkvt;                K = D_; Nn = D_;     bx = bid % 24;          by = bid / 24; }
        else if (bid < 1728) { W = Wkv; Wt = wqkvt + (size_t)D_ * D_; K = D_; Nn = 2 * D_; bx = (bid - 576) % 48;  by = (bid - 576) / 48; }
        else                 { W = Wp;  Wt = wpt;                  K = D_; Nn = D_;     bx = (bid - 1728) % 24; by = (bid - 1728) / 24; }
        const int k0 = by * 32, n0 = bx * 32;
        const int xx = tid & 31, y = tid >> 5;
        #pragma unroll
        for (int i = 0; i < 32; i += 8)
            t[y + i][xx] = W[(size_t)(k0 + y + i) * Nn + n0 + xx];
        __syncthreads();
        #pragma unroll
        for (int i = 0; i < 32; i += 8)
            Wt[(size_t)(n0 + y + i) * K + k0 + xx] = __float2half_rn(t[xx][y + i]);
    } else if (bid < 3456) {
        int i = (bid - 2304) * 256 + tid;
        if (i < D_ * 2 * D_ / 4) {
            float4 v = ((const float4*)Wkv)[i];
            ((__half2*)wkvh)[2 * i]     = __floats2half2_rn(v.x, v.y);
            ((__half2*)wkvh)[2 * i + 1] = __floats2half2_rn(v.z, v.w);
        }
    } else if (bid < 3465) {
        int i = (bid - 3456) * 256 + tid;
        if (i < D_) bqkv[i] = bq[i];
        else if (i < QKVW) bqkv[i] = bkv[i - D_];
    } else {
        int i = (bid - 3465) * 256 + tid;     // n4 = 8192*768/4 = 1572864
        if (i < B_ * N_ * D_ / 4) {
            float4 v = ((const float4*)x)[i];
            ((__half2*)xh)[2 * i]     = __floats2half2_rn(v.x, v.y);
            ((__half2*)xh)[2 * i + 1] = __floats2half2_rn(v.z, v.w);
        }
    }
}

// ---------------- generalized fp16 GEMM + bias (256x128 tile, ldmatrix) ---------
#define SAH  40
#define ABYT (256 * SAH * 2)
#define BBYT (128 * SAH * 2)
#define STG  (ABYT + BBYT)
#define GEMM_SMEM (3 * STG)

template <typename OutT>
__global__ __launch_bounds__(256, 1) void hgemm_bias(
    const __half* __restrict__ A, int lda, long zA,
    const __half* __restrict__ Bt, int ldb, long zB,
    const float* __restrict__ bias,
    OutT* __restrict__ C, int ldc, long zC,
    int Kdim)
{
    extern __shared__ __half smem[];
    A  += (size_t)blockIdx.z * zA;
    Bt += (size_t)blockIdx.z * zB;
    C  += (size_t)blockIdx.z * zC;

    const int tid  = threadIdx.x;
    const int warp = tid >> 5;
    const int lane = tid & 31;
    const int gid  = lane >> 2;
    const int tig  = lane & 3;
    const int wm   = (warp >> 1) * 64;
    const int wn   = (warp & 1)  * 64;
    const int bm   = blockIdx.y * 256;
    const int bn   = blockIdx.x * 128;

    const int crow = tid >> 2;
    const int cg   = (tid & 3) << 3;
    const __half* Agp = A  + (size_t)(bm + crow) * lda + cg;
    const __half* Bgp = Bt + (size_t)(bn + crow) * ldb + cg;
    const size_t a64 = (size_t)64 * lda;
    const size_t b64 = (size_t)64 * ldb;

    const int ktiles = Kdim >> 5;

    auto load_stage = [&](int s, int t) {
        __half* as = smem + s * (STG / 2);
        __half* bs = as + ABYT / 2;
        const int k0 = t << 5;
        #pragma unroll
        for (int i = 0; i < 4; i++)
            cp16(&as[(crow + i * 64) * SAH + cg], Agp + i * a64 + k0);
        #pragma unroll
        for (int i = 0; i < 2; i++)
            cp16(&bs[(crow + i * 64) * SAH + cg], Bgp + i * b64 + k0);
    };

    float acc[4][8][4];
    #pragma unroll
    for (int mt = 0; mt < 4; mt++)
        #pragma unroll
        for (int nt = 0; nt < 8; nt++)
            #pragma unroll
            for (int c = 0; c < 4; c++) acc[mt][nt][c] = 0.f;

    load_stage(0, 0); CP_COMMIT();
    if (ktiles > 1) load_stage(1, 1);
    CP_COMMIT();

    const int a_off = (wm + (lane & 15)) * SAH + ((lane >> 4) << 3);
    const int b_off = (wn + ((lane >> 4) << 3) + (lane & 7)) * SAH
                    + (((lane >> 3) & 1) << 3);

    for (int t = 0; t < ktiles; t++) {
        if (t + 2 < ktiles) load_stage((t + 2) % 3, t + 2);
        CP_COMMIT();
        CP_WAIT2();
        __syncthreads();

        const __half* as = smem + (t % 3) * (STG / 2);
        const __half* bs = as + ABYT / 2;
        #pragma unroll
        for (int ks = 0; ks < 2; ks++) {
            const int kh = ks << 4;
            unsigned afr[4][4], bfr[4][4];
            #pragma unroll
            for (int mt = 0; mt < 4; mt++)
                ldm_x4(afr[mt], as + a_off + mt * 16 * SAH + kh);
            #pragma unroll
            for (int np = 0; np < 4; np++)
                ldm_x4(bfr[np], bs + b_off + np * 16 * SAH + kh);
            #pragma unroll
            for (int mt = 0; mt < 4; mt++)
                #pragma unroll
                for (int nt = 0; nt < 8; nt++) {
                    const unsigned* bp = bfr[nt >> 1];
                    const int e = (nt & 1) << 1;
                    mma_f16(acc[mt][nt],
                            afr[mt][0], afr[mt][1], afr[mt][2], afr[mt][3],
                            bp[e], bp[e + 1]);
                }
        }
        __syncthreads();
    }

    #pragma unroll
    for (int mt = 0; mt < 4; mt++) {
        const int row0 = bm + wm + mt * 16 + gid;
        #pragma unroll
        for (int nt = 0; nt < 8; nt++) {
            const int col = bn + wn + nt * 8 + 2 * tig;
            const float b0 = bias[col], b1 = bias[col + 1];
            if constexpr (sizeof(OutT) == 4) {
                float2 o0, o1;
                o0.x = acc[mt][nt][0] + b0; o0.y = acc[mt][nt][1] + b1;
                o1.x = acc[mt][nt][2] + b0; o1.y = acc[mt][nt][3] + b1;
                *(float2*)&C[(size_t)row0 * ldc + col]       = o0;
                *(float2*)&C[(size_t)(row0 + 8) * ldc + col] = o1;
            } else {
                *(__half2*)&C[(size_t)row0 * ldc + col] =
                    __floats2half2_rn(acc[mt][nt][0] + b0, acc[mt][nt][1] + b1);
                *(__half2*)&C[(size_t)(row0 + 8) * ldc + col] =
                    __floats2half2_rn(acc[mt][nt][2] + b0, acc[mt][nt][3] + b1);
            }
        }
    }
}

// ---------------- dedicated t-GEMM (round-12 config; occ target 4) --------------
#define TST 72
__global__ __launch_bounds__(256, 4) void hgemm_t(
    const __half* __restrict__ qkv,    // A: lda=QKVW, head offset z*64
    const __half* __restrict__ wkvh,   // B: ldb=1536, head offset z*64
    __half* __restrict__ tt)           // C: ldc=H_*D_, head offset z*768
{
    __shared__ __half sA[128 * TST];
    __shared__ __half sB[64 * TST];

    const int tid  = threadIdx.x;
    const int warp = tid >> 5;
    const int lane = tid & 31;
    const int gid  = lane >> 2;
    const int tig  = lane & 3;
    const int wm   = (warp >> 1) * 32;   // 0,32,64,96
    const int wn   = (warp & 1)  * 32;   // 0,32
    const int bm   = blockIdx.y * 128;
    const int bn   = blockIdx.x * 64;
    const int z    = blockIdx.z;

    #pragma unroll
    for (int i = 0; i < 4; i++) {
        const int idx = tid + i * 256;
        const int row = idx >> 3, g = (idx & 7) << 3;
        cp16(&sA[row * TST + g],
             qkv + (size_t)(bm + row) * QKVW + z * DH + g);
    }
    #pragma unroll
    for (int i = 0; i < 2; i++) {
        const int idx = tid + i * 256;
        const int row = idx >> 3, g = (idx & 7) << 3;
        cp16(&sB[row * TST + g],
             wkvh + (size_t)(bn + row) * (2 * D_) + z * DH + g);
    }
    CP_COMMIT();
    CP_WAIT0();
    __syncthreads();

    float acc[2][4][4];
    #pragma unroll
    for (int mt = 0; mt < 2; mt++)
        #pragma unroll
        for (int nt = 0; nt < 4; nt++)
            #pragma unroll
            for (int c = 0; c < 4; c++) acc[mt][nt][c] = 0.f;

    const int a_off = (wm + (lane & 15)) * TST + ((lane >> 4) << 3);
    const int b_off = (wn + ((lane >> 4) << 3) + (lane & 7)) * TST
                    + (((lane >> 3) & 1) << 3);

    #pragma unroll
    for (int ks = 0; ks < 4; ks++) {
        const int kh = ks << 4;
        unsigned afr[2][4], bfr[2][4];
        #pragma unroll
        for (int mt = 0; mt < 2; mt++)
            ldm_x4(afr[mt], sA + a_off + mt * 16 * TST + kh);
        #pragma unroll
        for (int ng = 0; ng < 2; ng++)
            ldm_x4(bfr[ng], sB + b_off + ng * 16 * TST + kh);
        #pragma unroll
        for (int mt = 0; mt < 2; mt++)
            #pragma unroll
            for (int nt = 0; nt < 4; nt++) {
                const unsigned* bp = bfr[nt >> 1];
                const int e = (nt & 1) << 1;
                mma_f16(acc[mt][nt],
                        afr[mt][0], afr[mt][1], afr[mt][2], afr[mt][3],
                        bp[e], bp[e + 1]);
            }
    }

    __half* C = tt + (size_t)z * D_;
    #pragma unroll
    for (int mt = 0; mt < 2; mt++) {
        const int row0 = bm + wm + mt * 16 + gid;
        #pragma unroll
        for (int nt = 0; nt < 4; nt++) {
            const int col = bn + wn + nt * 8 + 2 * tig;
            *(__half2*)&C[(size_t)row0 * (H_ * D_) + col] =
                __floats2half2_rn(acc[mt][nt][0], acc[mt][nt][1]);
            *(__half2*)&C[(size_t)(row0 + 8) * (H_ * D_) + col] =
                __floats2half2_rn(acc[mt][nt][2], acc[mt][nt][3]);
        }
    }
}

// ---------------- svw GEMM ----------------
#define SVW_ABYT (256 * SAH * 2)
#define SVW_BBYT (64 * SAH * 2)
#define SVW_STG  (SVW_ABYT + SVW_BBYT)
#define SVW_SMEM (3 * SVW_STG)

__global__ __launch_bounds__(256, 1) void hgemm_svw(
    const __half* __restrict__ S,
    const __half* __restrict__ Wkvt,
    const float* __restrict__ bkv,
    const float* __restrict__ asum,
    __half* __restrict__ att)
{
    extern __shared__ __half smem[];
    const int h = blockIdx.z;
    const __half* A  = S + (size_t)h * (B_ * N_) * D_;
    const __half* Bt = Wkvt + (size_t)(D_ + h * DH) * D_;
    const float* bv  = bkv + D_ + h * DH;
    const float* ash = asum + (size_t)h * (B_ * N_);

    const int tid  = threadIdx.x;
    const int warp = tid >> 5;
    const int lane = tid & 31;
    const int gid  = lane >> 2;
    const int tig  = lane & 3;
    const int wm   = warp * 32;
    const int bm   = blockIdx.y * 256;

    const int crow = tid >> 2;
    const int cg   = (tid & 3) << 3;
    const __half* Agp = A  + (size_t)(bm + crow) * D_ + cg;
    const __half* Bgp = Bt + (size_t)crow * D_ + cg;
    const size_t a64 = (size_t)64 * D_;

    const int ktiles = D_ >> 5;

    auto load_stage = [&](int s, int t) {
        __half* as = smem + s * (SVW_STG / 2);
        __half* bs = as + SVW_ABYT / 2;
        const int k0 = t << 5;
        #pragma unroll
        for (int i = 0; i < 4; i++)
            cp16(&as[(crow + i * 64) * SAH + cg], Agp + i * a64 + k0);
        cp16(&bs[crow * SAH + cg], Bgp + k0);
    };

    float acc[2][8][4];
    #pragma unroll
    for (int mt = 0; mt < 2; mt++)
        #pragma unroll
        for (int nt = 0; nt < 8; nt++)
            #pragma unroll
            for (int c = 0; c < 4; c++) acc[mt][nt][c] = 0.f;

    load_stage(0, 0); CP_COMMIT();
    load_stage(1, 1); CP_COMMIT();

    const int a_off = (wm + (lane & 15)) * SAH + ((lane >> 4) << 3);
    const int b_off = (((lane >> 4) << 3) + (lane & 7)) * SAH
                    + (((lane >> 3) & 1) << 3);

    for (int t = 0; t < ktiles; t++) {
        if (t + 2 < ktiles) load_stage((t + 2) % 3, t + 2);
        CP_COMMIT();
        CP_WAIT2();
        __syncthreads();

        const __half* as = smem + (t % 3) * (SVW_STG / 2);
        const __half* bs = as + SVW_ABYT / 2;
        #pragma unroll
        for (int ks = 0; ks < 2; ks++) {
            const int kh = ks << 4;
            unsigned afr[2][4], bfr[4][4];
            #pragma unroll
            for (int mt = 0; mt < 2; mt++)
                ldm_x4(afr[mt], as + a_off + mt * 16 * SAH + kh);
            #pragma unroll
            for (int np = 0; np < 4; np++)
                ldm_x4(bfr[np], bs + b_off + np * 16 * SAH + kh);
            #pragma unroll
            for (int mt = 0; mt < 2; mt++)
                #pragma unroll
                for (int nt = 0; nt < 8; nt++) {
                    const unsigned* bp = bfr[nt >> 1];
                    const int e = (nt & 1) << 1;
                    mma_f16(acc[mt][nt],
                            afr[mt][0], afr[mt][1], afr[mt][2], afr[mt][3],
                            bp[e], bp[e + 1]);
                }
        }
        __syncthreads();
    }

    #pragma unroll
    for (int mt = 0; mt < 2; mt++) {
        const int row0 = bm + wm + mt * 16 + gid;
        const float as0 = ash[row0], as1 = ash[row0 + 8];
        #pragma unroll
        for (int nt = 0; nt < 8; nt++) {
            const int col = nt * 8 + 2 * tig;
            const float b0 = bv[col], b1 = bv[col + 1];
            __half2* c0 = (__half2*)&att[(size_t)row0 * D_ + h * DH + col];
            __half2* c1 = (__half2*)&att[(size_t)(row0 + 8) * D_ + h * DH + col];
            float2 p0 = __half22float2(*c0);
            float2 p1 = __half22float2(*c1);
            *c0 = __floats2half2_rn(acc[mt][nt][0] + as0 * b0 + p0.x,
                                    acc[mt][nt][1] + as0 * b1 + p0.y);
            *c1 = __floats2half2_rn(acc[mt][nt][2] + as1 * b0 + p1.x,
                                    acc[mt][nt][3] + as1 * b1 + p1.y);
        }
    }
}

// ---------------- sim logits (fp32 sim input) ----------------
__global__ __launch_bounds__(256) void logits_sim_kernel(
    const float* __restrict__ sim,
    const __half* __restrict__ t,
    float* __restrict__ ls)
{
    __shared__ float  ssim[M_ * D_];
    __shared__ __half st[H_ * D_];
    const int bn = blockIdx.x;
    const int tid = threadIdx.x;
    const float4* sg = (const float4*)(sim + (size_t)bn * M_ * D_);
    float4* sd = (float4*)ssim;
    for (int i = tid; i < M_ * D_ / 4; i += 256) sd[i] = sg[i];
    const float4* tg = (const float4*)(t + (size_t)bn * H_ * D_);
    float4* td = (float4*)st;
    for (int i = tid; i < H_ * D_ / 8; i += 256) td[i] = tg[i];
    __syncthreads();

    const int warp = tid >> 5, lane = tid & 31;
    const int b = bn >> 9, n = bn & 511;
    const float2* s2 = (const float2*)ssim;
    const __half2* t2 = (const __half2*)st;
    for (int d = warp; d < H_ * M_; d += 8) {
        const int h = d >> 3, m = d & 7;
        float a = 0.f;
        #pragma unroll
        for (int j = 0; j < 12; j++) {
            float2 x = s2[m * 384 + lane + 32 * j];
            float2 y = __half22float2(t2[h * 384 + lane + 32 * j]);
            a += x.x * y.x + x.y * y.y;
        }
        #pragma unroll
        for (int o = 16; o; o >>= 1) a += __shfl_xor_sync(0xffffffffu, a, o);
        if (lane == 0)
            ls[(((size_t)b * H_ + h) * N_ + n) * M_ + m] = a;
    }
}

// ---------------- s-pass (fp32 sim input) ----------------
__global__ __launch_bounds__(256) void spass_kernel(
    const float* __restrict__ sim,
    const float* __restrict__ w,
    __half* __restrict__ s)
{
    __shared__ float ssim[M_ * D_];
    __shared__ float sw[H_ * M_];
    const int bn = blockIdx.x;
    const int tid = threadIdx.x;
    const float4* sg = (const float4*)(sim + (size_t)bn * M_ * D_);
    float4* sd = (float4*)ssim;
    for (int i = tid; i < M_ * D_ / 4; i += 256) sd[i] = sg[i];
    if (tid < H_ * M_) {
        int h = tid >> 3, m = tid & 7;
        sw[tid] = w[((size_t)h * (B_ * N_) + bn) * M_ + m];
    }
    __syncthreads();

    const float2* s2 = (const float2*)ssim;
    for (int idx = tid; idx < H_ * 384; idx += 256) {
        const int h = idx / 384, c2 = idx % 384;
        float ax = 0.f, ay = 0.f;
        #pragma unroll
        for (int m = 0; m < M_; m++) {
            float2 v = s2[m * 384 + c2];
            float wm_ = sw[h * M_ + m];
            ax += wm_ * v.x; ay += wm_ * v.y;
        }
        ((__half2*)s)[((size_t)h * (B_ * N_) + bn) * 384 + c2] =
            __floats2half2_rn(ax, ay);
    }
}

// ---------------- tensor-core flash attention (128 queries, 8 warps) ----------
#define SQV 72
#define QSZ (128 * SQV)
#define TSZ (64 * SQV)
#define ATTN_SMEM_MMA ((QSZ + 6 * TSZ) * 2)   // 73728 B

__global__ __launch_bounds__(256, 2) void attn_mma_kernel(
    const __half* __restrict__ qkv,
    const float*  __restrict__ bkv,
    const float*  __restrict__ ls,
    __half* __restrict__ outa,
    float* __restrict__ wg,
    float* __restrict__ asum)
{
    extern __shared__ __half smh[];
    __half* sQ = smh;
    __half* sK = sQ + QSZ;
    __half* sV = sK + 3 * TSZ;

    const int tid = threadIdx.x;
    const int warp = tid >> 5, lane = tid & 31;
    const int gid = lane >> 2, tig = lane & 3;
    const int n0 = blockIdx.x * 128, h = blockIdx.y, b = blockIdx.z;
    const int wq = warp * 16;
    const float scale = kSCALE;
    const int bn0 = b * N_ + n0;

    {
        const int row = tid >> 1, g0 = (tid & 1) << 5;
        const __half* src = qkv + (size_t)(bn0 + row) * QKVW + h * DH + g0;
        #pragma unroll
        for (int i = 0; i < 4; i++)
            cp16(&sQ[row * SQV + g0 + i * 8], src + i * 8);
    }
    auto load_tile = [&](int st, int kt) {
        const int row = tid >> 2, g = (tid & 3) << 4;
        size_t go = (size_t)(b * N_ + kt * 64 + row) * QKVW + D_ + h * DH + g;
        cp16(&sK[st * TSZ + row * SQV + g],     qkv + go);
        cp16(&sK[st * TSZ + row * SQV + g + 8], qkv + go + 8);
        cp16(&sV[st * TSZ + row * SQV + g],     qkv + go + D_);
        cp16(&sV[st * TSZ + row * SQV + g + 8], qkv + go + D_ + 8);
    };
    load_tile(0, 0); CP_COMMIT();
    load_tile(1, 1); CP_COMMIT();

    float m_[2] = {-1e30f, -1e30f}, l_[2] = {0.f, 0.f};
    float o[8][4];
    #pragma unroll
    for (int nt = 0; nt < 8; nt++)
        #pragma unroll
        for (int c = 0; c < 4; c++) o[nt][c] = 0.f;

    unsigned qa[4][4];
    const int a_off = (wq + (lane & 15)) * SQV + ((lane >> 4) << 3);
    const int kb_off = (((lane >> 4) << 3) + (lane & 7)) * SQV
                     + (((lane >> 3) & 1) << 3);
    const int vb_off = (((lane >> 3) & 1) * 8 + (lane & 7)) * SQV
                     + ((lane >> 4) << 3);
    bool qloaded = false;

    for (int kt = 0; kt < 8; kt++) {
        if (kt + 2 < 8) load_tile((kt + 2) % 3, kt + 2);
        CP_COMMIT();
        CP_WAIT2();
        __syncthreads();

        if (!qloaded) {
            #pragma unroll
            for (int ks = 0; ks < 4; ks++)
                ldm_x4(qa[ks], sQ + a_off + ks * 16);
            qloaded = true;
        }

        const __half* kb = sK + (kt % 3) * TSZ;
        const __half* vb = sV + (kt % 3) * TSZ;

        float sc[8][4];
        #pragma unroll
        for (int nt = 0; nt < 8; nt++)
            #pragma unroll
            for (int c = 0; c < 4; c++) sc[nt][c] = 0.f;
        #pragma unroll
        for (int ks = 0; ks < 4; ks++) {
            unsigned kf[4][4];
            #pragma unroll
            for (int ng = 0; ng < 4; ng++)
                ldm_x4(kf[ng], kb + kb_off + ng * 16 * SQV + ks * 16);
            #pragma unroll
            for (int nt = 0; nt < 8; nt++) {
                const unsigned* bp = kf[nt >> 1];
                const int e = (nt & 1) << 1;
                mma_f16(sc[nt], qa[ks][0], qa[ks][1], qa[ks][2], qa[ks][3],
                        bp[e], bp[e + 1]);
            }
        }
        #pragma unroll
        for (int nt = 0; nt < 8; nt++)
            #pragma unroll
            for (int c = 0; c < 4; c++) sc[nt][c] *= scale;

        #pragma unroll
        for (int s = 0; s < 2; s++) {
            const int e = s << 1;
            float tmax = -1e30f;
            #pragma unroll
            for (int nt = 0; nt < 8; nt++)
                tmax = fmaxf(tmax, fmaxf(sc[nt][e], sc[nt][e + 1]));
            tmax = fmaxf(tmax, __shfl_xor_sync(0xffffffffu, tmax, 1));
            tmax = fmaxf(tmax, __shfl_xor_sync(0xffffffffu, tmax, 2));
            float nm = fmaxf(m_[s], tmax);
            float corr = __expf(m_[s] - nm);
            float sum = 0.f;
            #pragma unroll
            for (int nt = 0; nt < 8; nt++) {
                sc[nt][e]     = __expf(sc[nt][e] - nm);
                sc[nt][e + 1] = __expf(sc[nt][e + 1] - nm);
                sum += sc[nt][e] + sc[nt][e + 1];
            }
            sum += __shfl_xor_sync(0xffffffffu, sum, 1);
            sum += __shfl_xor_sync(0xffffffffu, sum, 2);
            l_[s] = l_[s] * corr + sum;
            m_[s] = nm;
            #pragma unroll
            for (int nt = 0; nt < 8; nt++) {
                o[nt][e]     *= corr;
                o[nt][e + 1] *= corr;
            }
        }

        unsigned pa[4][4];
        #pragma unroll
        for (int kc = 0; kc < 4; kc++) {
            pa[kc][0] = packh2(sc[2 * kc][0],     sc[2 * kc][1]);
            pa[kc][1] = packh2(sc[2 * kc][2],     sc[2 * kc][3]);
            pa[kc][2] = packh2(sc[2 * kc + 1][0], sc[2 * kc + 1][1]);
            pa[kc][3] = packh2(sc[2 * kc + 1][2], sc[2 * kc + 1][3]);
        }

        #pragma unroll
        for (int kc = 0; kc < 4; kc++) {
            unsigned vf[4][4];
            #pragma unroll
            for (int ng = 0; ng < 4; ng++)
                ldm_x4t(vf[ng], vb + vb_off + kc * 16 * SQV + ng * 16);
            #pragma unroll
            for (int nt = 0; nt < 8; nt++) {
                const unsigned* bp = vf[nt >> 1];
                const int e = (nt & 1) << 1;
                mma_f16(o[nt], pa[kc][0], pa[kc][1], pa[kc][2], pa[kc][3],
                        bp[e], bp[e + 1]);
            }
        }
        __syncthreads();
    }

    #pragma unroll
    for (int s = 0; s < 2; s++) {
        const int rl = wq + gid + s * 8;
        const int e = s << 1;

        float qbk = 0.f;
        {
            const __half2* qp = (const __half2*)&sQ[rl * SQV + tig * 16];
            const float* bk = bkv + h * DH + tig * 16;
            #pragma unroll
            for (int j = 0; j < 8; j++) {
                float2 f = __half22float2(qp[j]);
                qbk += f.x * bk[2 * j] + f.y * bk[2 * j + 1];
            }
            qbk += __shfl_xor_sync(0xffffffffu, qbk, 1);
            qbk += __shfl_xor_sync(0xffffffffu, qbk, 2);
        }

        float2 raw = *(const float2*)&ls[(((size_t)b * H_ + h) * N_ + n0 + rl) * M_ + 2 * tig];
        float lg0 = scale * (raw.x + qbk);
        float lg1 = scale * (raw.y + qbk);

        float tmax = fmaxf(lg0, lg1);
        tmax = fmaxf(tmax, __shfl_xor_sync(0xffffffffu, tmax, 1));
        tmax = fmaxf(tmax, __shfl_xor_sync(0xffffffffu, tmax, 2));
        float nm = fmaxf(m_[s], tmax);
        float corr = __expf(m_[s] - nm);
        float p0 = __expf(lg0 - nm);
        float p1 = __expf(lg1 - nm);
        float ps = p0 + p1;
        ps += __shfl_xor_sync(0xffffffffu, ps, 1);
        ps += __shfl_xor_sync(0xffffffffu, ps, 2);
        float lnew = l_[s] * corr + ps;
        float inv = 1.f / lnew;

        size_t widx = (size_t)h * (B_ * N_) + bn0 + rl;
        float2 wout; wout.x = p0 * inv; wout.y = p1 * inv;
        *(float2*)&wg[widx * M_ + 2 * tig] = wout;
        if (tig == 0) asum[widx] = ps * inv;

        const float ci = corr * inv;
        __half2* op = (__half2*)&outa[(size_t)(bn0 + rl) * D_ + h * DH];
        #pragma unroll
        for (int nt = 0; nt < 8; nt++)
            op[nt * 4 + tig] = __floats2half2_rn(o[nt][e] * ci, o[nt][e + 1] * ci);
    }
}

// ---------------- launch ----------------
extern "C" void kernel_launch(void* const* d_in, const int* in_sizes, int n_in,
                              void* d_out, int out_size)
{
    const float* x   = (const float*)d_in[0];
    const float* sim = (const float*)d_in[1];
    const float* Wq  = (const float*)d_in[2];
    const float* bq  = (const float*)d_in[3];
    const float* Wkv = (const float*)d_in[4];
    const float* bkv = (const float*)d_in[5];
    const float* Wp  = (const float*)d_in[6];
    const float* bp  = (const float*)d_in[7];
    float* out = (float*)d_out;

    __half *qkv, *att, *xh, *tt, *ss, *wqkvt, *wkvh, *wpt;
    float  *ls, *wg, *asum, *bqkv;
    cudaGetSymbolAddress((void**)&qkv,   g_qkv);
    cudaGetSymbolAddress((void**)&att,   g_att);
    cudaGetSymbolAddress((void**)&xh,    g_xh);
    cudaGetSymbolAddress((void**)&tt,    g_t);
    cudaGetSymbolAddress((void**)&ss,    g_s);
    cudaGetSymbolAddress((void**)&ls,    g_ls);
    cudaGetSymbolAddress((void**)&wg,    g_w);
    cudaGetSymbolAddress((void**)&asum,  g_asum);
    cudaGetSymbolAddress((void**)&wqkvt, g_wqkvt);
    cudaGetSymbolAddress((void**)&wkvh,  g_wkvh);
    cudaGetSymbolAddress((void**)&wpt,   g_wpt);
    cudaGetSymbolAddress((void**)&bqkv,  g_bqkv);

    cudaFuncSetAttribute(attn_mma_kernel,
                         cudaFuncAttributeMaxDynamicSharedMemorySize, ATTN_SMEM_MMA);
    cudaFuncSetAttribute(hgemm_bias<float>,
                         cudaFuncAttributeMaxDynamicSharedMemorySize, GEMM_SMEM);
    cudaFuncSetAttribute(hgemm_bias<__half>,
                         cudaFuncAttributeMaxDynamicSharedMemorySize, GEMM_SMEM);
    cudaFuncSetAttribute(hgemm_svw,
                         cudaFuncAttributeMaxDynamicSharedMemorySize, SVW_SMEM);

    const int BN = B_ * N_;

    // 0: merged prep (weight transposes + f2h Wkv + bias concat + f2h x)
    prep_weights<<<3465 + BN * D_ / 4 / 256, 256>>>(
        Wq, Wkv, Wp, x, bq, bkv, wqkvt, wkvh, wpt, xh, bqkv);
    // 1: merged QKV projection
    hgemm_bias<__half><<<dim3(QKVW / 128, BN / 256), 256, GEMM_SMEM>>>(
        xh, D_, 0, wqkvt, D_, 0, bqkv, qkv, QKVW, 0, D_);
    // 2: t_h = q_h @ Wk_h^T
    hgemm_t<<<dim3(D_ / 64, BN / 128, H_), 256>>>(qkv, wkvh, tt);
    // 3: raw sim logits
    logits_sim_kernel<<<BN, 256>>>(sim, tt, ls);
    // 4: flash attention
    attn_mma_kernel<<<dim3(N_ / 128, H_, B_), 256, ATTN_SMEM_MMA>>>(
        qkv, bkv, ls, att, wg, asum);
    // 5: s-pass
    spass_kernel<<<BN, 256>>>(sim, wg, ss);
    // 6: att += s_h @ Wv_h + asum*bv_h
    hgemm_svw<<<dim3(1, BN / 256, H_), 256, SVW_SMEM>>>(
        ss, wqkvt + (size_t)D_ * D_, bkv, asum, att);
    // 7: final projection
    hgemm_bias<float><<<dim3(D_ / 128, BN / 256), 256, GEMM_SMEM>>>(
        att, D_, 0, wpt, D_, 0, bp, out, D_, 0, D_);
}